// round 1
// baseline (speedup 1.0000x reference)
#include <cuda_runtime.h>
#include <math.h>
#include <stdint.h>

#define BSZ   4
#define TLEN  2048
#define CDIM  1024
#define NHEAD 16
#define HD    64
#define QK_SCALE 0.125f   // 1/sqrt(64)

#define SCRATCH_ELEMS (BSZ * NHEAD * TLEN * HD)   // 8,388,608 floats = 32 MB each

__device__ float g_q[SCRATCH_ELEMS];
__device__ float g_k[SCRATCH_ELEMS];
__device__ float g_v[SCRATCH_ELEMS];

// ---------------------------------------------------------------------------
// Kernel 1: QKV projection.  out[m][n] = sum_k x[m][k] * W[n][k] + bias[n]
// M = B*T = 8192, N = 3*C = 3072, K = C = 1024.
// Writes directly into g_q/g_k/g_v in [B, H, T, hd] layout.
// Classic 64x64 block tile, 4x4 per thread, BK=16, 256 threads.
// ---------------------------------------------------------------------------
#define GM 64
#define GN 64
#define GK 16

__global__ __launch_bounds__(256) void qkv_gemm_kernel(
    const float* __restrict__ x,
    const float* __restrict__ w,
    const float* __restrict__ bias)
{
    __shared__ float As[GK][GM + 4];
    __shared__ float Bs[GK][GN + 4];

    const int tid = threadIdx.x;
    const int tx  = tid & 15;        // 0..15  (n direction)
    const int ty  = tid >> 4;        // 0..15  (m direction)
    const int m0  = blockIdx.y * GM;
    const int n0  = blockIdx.x * GN;

    // cooperative-load mapping: each thread loads one float4 of A and one of B
    const int lrow = tid >> 2;           // 0..63
    const int lk4  = (tid & 3) << 2;     // 0,4,8,12

    float acc[4][4];
#pragma unroll
    for (int i = 0; i < 4; i++)
#pragma unroll
        for (int j = 0; j < 4; j++) acc[i][j] = 0.f;

    for (int k0 = 0; k0 < CDIM; k0 += GK) {
        float4 av = *(const float4*)(x + (size_t)(m0 + lrow) * CDIM + k0 + lk4);
        float4 bv = *(const float4*)(w + (size_t)(n0 + lrow) * CDIM + k0 + lk4);
        As[lk4 + 0][lrow] = av.x;
        As[lk4 + 1][lrow] = av.y;
        As[lk4 + 2][lrow] = av.z;
        As[lk4 + 3][lrow] = av.w;
        Bs[lk4 + 0][lrow] = bv.x;
        Bs[lk4 + 1][lrow] = bv.y;
        Bs[lk4 + 2][lrow] = bv.z;
        Bs[lk4 + 3][lrow] = bv.w;
        __syncthreads();

#pragma unroll
        for (int kk = 0; kk < GK; kk++) {
            float4 a4 = *(const float4*)&As[kk][ty << 2];
            float4 b4 = *(const float4*)&Bs[kk][tx << 2];
            float a[4] = {a4.x, a4.y, a4.z, a4.w};
            float b[4] = {b4.x, b4.y, b4.z, b4.w};
#pragma unroll
            for (int i = 0; i < 4; i++)
#pragma unroll
                for (int j = 0; j < 4; j++)
                    acc[i][j] = fmaf(a[i], b[j], acc[i][j]);
        }
        __syncthreads();
    }

    // Epilogue: add bias, scatter into [B, H, T, hd] scratch.
    // n0 is a multiple of 64 -> the whole 64-wide tile lies in one head of one of Q/K/V.
    const int which = n0 / CDIM;               // 0=Q, 1=K, 2=V
    const int h     = (n0 % CDIM) / HD;
    float* dst = (which == 0) ? g_q : (which == 1) ? g_k : g_v;

#pragma unroll
    for (int i = 0; i < 4; i++) {
        const int m = m0 + (ty << 2) + i;
        const int b = m / TLEN;
        const int t = m % TLEN;
        float* rowp = dst + (((size_t)(b * NHEAD + h) * TLEN) + t) * HD;
#pragma unroll
        for (int j = 0; j < 4; j++) {
            const int n = n0 + (tx << 2) + j;
            const int d = n % HD;
            rowp[d] = acc[i][j] + bias[n];
        }
    }
}

// ---------------------------------------------------------------------------
// Kernel 2: causal flash attention, fp32.
// One thread owns one q row (q[64] and o[64] in registers).
// Block = 128 threads = 128 q rows of one (b,h); K/V staged in smem 64 keys
// at a time; online softmax with rescale-only-on-new-max.
// ---------------------------------------------------------------------------
#define AQ 128   // q rows per block
#define AK 64    // keys per smem tile

__global__ __launch_bounds__(128, 3) void attn_kernel(float* __restrict__ out)
{
    __shared__ float Ks[AK][HD];
    __shared__ float Vs[AK][HD];

    const int bh  = blockIdx.y;                                // 0..63
    const int b   = bh / NHEAD;
    const int h   = bh % NHEAD;
    const int r0  = (gridDim.x - 1 - blockIdx.x) * AQ;         // heavy tiles launch first
    const int row = r0 + threadIdx.x;

    const float* kbase = g_k + (size_t)bh * TLEN * HD;
    const float* vbase = g_v + (size_t)bh * TLEN * HD;

    // load q row, pre-scaled by 1/sqrt(hd)
    float q[HD];
    {
        const float4* qp = (const float4*)(g_q + ((size_t)bh * TLEN + row) * HD);
#pragma unroll
        for (int d4 = 0; d4 < HD / 4; d4++) {
            float4 t = qp[d4];
            q[4 * d4 + 0] = t.x * QK_SCALE;
            q[4 * d4 + 1] = t.y * QK_SCALE;
            q[4 * d4 + 2] = t.z * QK_SCALE;
            q[4 * d4 + 3] = t.w * QK_SCALE;
        }
    }

    float o[HD];
#pragma unroll
    for (int d = 0; d < HD; d++) o[d] = 0.f;
    float m = -INFINITY;
    float l = 0.f;

    const int nkt = r0 / AK + 2;   // covers keys 0 .. r0+127

    for (int kt = 0; kt < nkt; kt++) {
        __syncthreads();   // previous tile fully consumed
        {
            const float4* srcK = (const float4*)(kbase + (size_t)kt * AK * HD);
            const float4* srcV = (const float4*)(vbase + (size_t)kt * AK * HD);
            float4* dK = (float4*)&Ks[0][0];
            float4* dV = (float4*)&Vs[0][0];
#pragma unroll
            for (int i = 0; i < (AK * HD / 4) / AQ; i++) {   // 8 float4 per thread per tile
                const int idx = threadIdx.x + i * AQ;
                dK[idx] = srcK[idx];
                dV[idx] = srcV[idx];
            }
        }
        __syncthreads();

        const int ktbase = kt * AK;
#pragma unroll 1
        for (int j = 0; j < AK; j++) {
            const int jj = ktbase + j;
            if (jj > row) break;   // causal: keys are in order, remainder also masked

            // s = q . k[j]   (4 partial chains for ILP)
            const float4* kr = (const float4*)Ks[j];
            float s0 = 0.f, s1 = 0.f, s2 = 0.f, s3 = 0.f;
#pragma unroll
            for (int d4 = 0; d4 < HD / 4; d4++) {
                float4 kv = kr[d4];
                s0 = fmaf(q[4 * d4 + 0], kv.x, s0);
                s1 = fmaf(q[4 * d4 + 1], kv.y, s1);
                s2 = fmaf(q[4 * d4 + 2], kv.z, s2);
                s3 = fmaf(q[4 * d4 + 3], kv.w, s3);
            }
            const float s = (s0 + s1) + (s2 + s3);

            if (s > m) {            // rare after warmup: rescale running state
                const float c = __expf(m - s);   // m=-inf on first key -> c=0
                l *= c;
#pragma unroll
                for (int d = 0; d < HD; d++) o[d] *= c;
                m = s;
            }
            const float p = __expf(s - m);
            l += p;

            const float4* vr = (const float4*)Vs[j];
#pragma unroll
            for (int d4 = 0; d4 < HD / 4; d4++) {
                float4 vv = vr[d4];
                o[4 * d4 + 0] = fmaf(p, vv.x, o[4 * d4 + 0]);
                o[4 * d4 + 1] = fmaf(p, vv.y, o[4 * d4 + 1]);
                o[4 * d4 + 2] = fmaf(p, vv.z, o[4 * d4 + 2]);
                o[4 * d4 + 3] = fmaf(p, vv.w, o[4 * d4 + 3]);
            }
        }
    }

    // finalize + write y[b][t][h*64 + d]
    const float inv = 1.f / l;     // l >= 1 (max key contributes exactly 1)
    float4* op = (float4*)(out + ((size_t)b * TLEN + row) * CDIM + h * HD);
#pragma unroll
    for (int d4 = 0; d4 < HD / 4; d4++) {
        float4 v;
        v.x = o[4 * d4 + 0] * inv;
        v.y = o[4 * d4 + 1] * inv;
        v.z = o[4 * d4 + 2] * inv;
        v.w = o[4 * d4 + 3] * inv;
        op[d4] = v;
    }
}

// ---------------------------------------------------------------------------
extern "C" void kernel_launch(void* const* d_in, const int* in_sizes, int n_in,
                              void* d_out, int out_size)
{
    const float* x    = (const float*)d_in[0];   // [4, 2048, 1024]
    const float* w    = (const float*)d_in[1];   // [3072, 1024]
    const float* bias = (const float*)d_in[2];   // [3072]
    float* out        = (float*)d_out;           // [4, 2048, 1024]

    (void)in_sizes; (void)n_in; (void)out_size;

    dim3 ggrid(3 * CDIM / GN, (BSZ * TLEN) / GM);   // (48, 128)
    qkv_gemm_kernel<<<ggrid, 256>>>(x, w, bias);

    dim3 agrid(TLEN / AQ, BSZ * NHEAD);             // (16, 64)
    attn_kernel<<<agrid, 128>>>(out);
}

// round 3
// speedup vs baseline: 1.5795x; 1.5795x over previous
#include <cuda_runtime.h>
#include <math.h>
#include <stdint.h>

#define BSZ   4
#define TLEN  2048
#define CDIM  1024
#define NHEAD 16
#define HD    64
#define QK_SCALE 0.125f   // 1/sqrt(64)

#define SCRATCH_ELEMS (BSZ * NHEAD * TLEN * HD)   // 8,388,608 floats = 32 MB each

__device__ float g_q[SCRATCH_ELEMS];
__device__ float g_k[SCRATCH_ELEMS];
__device__ float g_v[SCRATCH_ELEMS];

// ===========================================================================
// Helpers — baseline-ISA only (cp.async + mma.sync; NO tcgen05 on sm_100)
// ===========================================================================
__device__ __forceinline__ uint32_t smem_u32(const void* p) {
    uint32_t a;
    asm("{ .reg .u64 t; cvta.to.shared.u64 t, %1; cvt.u32.u64 %0, t; }"
        : "=r"(a) : "l"(p));
    return a;
}

__device__ __forceinline__ void cp_async16(uint32_t saddr, const void* gaddr) {
    asm volatile("cp.async.cg.shared.global [%0], [%1], 16;"
                 :: "r"(saddr), "l"(gaddr) : "memory");
}
__device__ __forceinline__ void cp_async_commit() {
    asm volatile("cp.async.commit_group;" ::: "memory");
}
template <int N>
__device__ __forceinline__ void cp_async_wait() {
    asm volatile("cp.async.wait_group %0;" :: "n"(N) : "memory");
}

__device__ __forceinline__ uint32_t f32_to_tf32(float f) {
    uint32_t r;
    asm("cvt.rna.tf32.f32 %0, %1;" : "=r"(r) : "f"(f));
    return r;
}

// D += A(16x8, row) * B(8x8, col), tf32 inputs, f32 accumulate
__device__ __forceinline__ void mma_16n8k8_tf32(
    float* d, uint32_t a0, uint32_t a1, uint32_t a2, uint32_t a3,
    uint32_t b0, uint32_t b1)
{
    asm volatile(
        "mma.sync.aligned.m16n8k8.row.col.f32.tf32.tf32.f32 "
        "{%0,%1,%2,%3}, {%4,%5,%6,%7}, {%8,%9}, {%0,%1,%2,%3};"
        : "+f"(d[0]), "+f"(d[1]), "+f"(d[2]), "+f"(d[3])
        : "r"(a0), "r"(a1), "r"(a2), "r"(a3), "r"(b0), "r"(b1));
}

// ===========================================================================
// Kernel 1: QKV projection via mma.sync tf32.
//   D[m][n] = sum_k x[m][k] * W[n][k] + bias[n]
//   M=8192, N=3072, K=1024. CTA 128x128, warp tile 32x64, K staged 32 floats.
// ===========================================================================
#define TM 128
#define TN 128
#define TK 32
#define NSTG 3
#define LDP 36                              // padded row stride (floats)
#define A_STG_FLTS (TM * LDP)               // 4608
#define B_STG_FLTS (TN * LDP)               // 4608
#define STG_FLTS   (A_STG_FLTS + B_STG_FLTS)
#define NCHUNK (CDIM / TK)                  // 32
#define DYN_SMEM (NSTG * STG_FLTS * 4)      // 110592 B

__global__ void __launch_bounds__(256, 2) qkv_mma_kernel(
    const float* __restrict__ x,
    const float* __restrict__ w,
    const float* __restrict__ bias)
{
    extern __shared__ float smem[];

    const int tid = threadIdx.x;
    const int wid = tid >> 5;
    const int lid = tid & 31;
    const int g   = lid >> 2;               // group id (0..7)
    const int c   = lid & 3;                // thread-in-group (0..3)
    const int warp_m = (wid & 3) * 32;      // 0,32,64,96
    const int warp_n = (wid >> 2) * 64;     // 0,64
    const int m0  = blockIdx.y * TM;
    const int n0  = blockIdx.x * TN;

    const uint32_t sbase = smem_u32(smem);

    // ---- cp.async mapping: 8 x 16B chunks per thread per stage ----
    // ids 0..1023 -> A (128 rows x 8 chunks), 1024..2047 -> B.
    const char* gptr[8];
    uint32_t    soff[8];                    // byte offset within a stage
#pragma unroll
    for (int t = 0; t < 8; t++) {
        const int cc = tid + t * 256;
        if (cc < 1024) {
            const int row = cc >> 3, o = cc & 7;
            gptr[t] = (const char*)(x + (size_t)(m0 + row) * CDIM) + o * 16;
            soff[t] = (uint32_t)(row * LDP * 4 + o * 16);
        } else {
            const int cb = cc - 1024;
            const int row = cb >> 3, o = cb & 7;
            gptr[t] = (const char*)(w + (size_t)(n0 + row) * CDIM) + o * 16;
            soff[t] = (uint32_t)(A_STG_FLTS * 4 + row * LDP * 4 + o * 16);
        }
    }

#define LOAD_STAGE(chunk)                                                   \
    do {                                                                    \
        const uint32_t sb_ = sbase + ((chunk) % NSTG) * (STG_FLTS * 4);     \
        const int gof_ = (chunk) * 128;  /* 32 floats */                    \
        _Pragma("unroll")                                                   \
        for (int t = 0; t < 8; t++)                                         \
            cp_async16(sb_ + soff[t], gptr[t] + gof_);                      \
        cp_async_commit();                                                  \
    } while (0)

    float acc[2][8][4];
#pragma unroll
    for (int mb = 0; mb < 2; mb++)
#pragma unroll
        for (int nb = 0; nb < 8; nb++)
#pragma unroll
            for (int r = 0; r < 4; r++) acc[mb][nb][r] = 0.f;

    // prologue
    LOAD_STAGE(0);
    LOAD_STAGE(1);

    for (int i = 0; i < NCHUNK; i++) {
        cp_async_wait<NSTG - 2>();          // chunk i landed
        __syncthreads();

        if (i + 2 < NCHUNK) { LOAD_STAGE(i + 2); }
        else                { cp_async_commit(); }

        const float* As = smem + (i % NSTG) * STG_FLTS;
        const float* Bs = As + A_STG_FLTS;

#pragma unroll
        for (int ks = 0; ks < 4; ks++) {
            const int k = ks * 8;
            // A fragments: 2 m16 blocks
            uint32_t af[2][4];
#pragma unroll
            for (int mb = 0; mb < 2; mb++) {
                const float* ap = As + (warp_m + mb * 16 + g) * LDP + k + c;
                af[mb][0] = f32_to_tf32(ap[0]);
                af[mb][1] = f32_to_tf32(ap[8 * LDP]);
                af[mb][2] = f32_to_tf32(ap[4]);
                af[mb][3] = f32_to_tf32(ap[8 * LDP + 4]);
            }
            // B fragments: 8 n8 blocks
            uint32_t bf[8][2];
#pragma unroll
            for (int nb = 0; nb < 8; nb++) {
                const float* bp = Bs + (warp_n + nb * 8 + g) * LDP + k + c;
                bf[nb][0] = f32_to_tf32(bp[0]);
                bf[nb][1] = f32_to_tf32(bp[4]);
            }
#pragma unroll
            for (int mb = 0; mb < 2; mb++)
#pragma unroll
                for (int nb = 0; nb < 8; nb++)
                    mma_16n8k8_tf32(acc[mb][nb],
                                    af[mb][0], af[mb][1], af[mb][2], af[mb][3],
                                    bf[nb][0], bf[nb][1]);
        }
        __syncthreads();                    // stage consumed before overwrite
    }

    // ---- epilogue: bias + scatter into [B, H, T, 64] scratch ----
    const int which = n0 >> 10;             // 0=Q 1=K 2=V (TN=128 divides 1024)
    float* dst = (which == 0) ? g_q : (which == 1) ? g_k : g_v;

#pragma unroll
    for (int mb = 0; mb < 2; mb++) {
        const int mA = m0 + warp_m + mb * 16 + g;
        const int mB = mA + 8;
        const int bA = mA >> 11, tA = mA & (TLEN - 1);
        const int bB = mB >> 11, tB = mB & (TLEN - 1);
#pragma unroll
        for (int nb = 0; nb < 8; nb++) {
            const int n = n0 + warp_n + nb * 8 + 2 * c;
            const int h = (n >> 6) & (NHEAD - 1);
            const int d = n & 63;
            const float bx = __ldg(bias + n);
            const float by = __ldg(bias + n + 1);
            float* pA = dst + (((size_t)(bA * NHEAD + h) * TLEN) + tA) * HD + d;
            float* pB = dst + (((size_t)(bB * NHEAD + h) * TLEN) + tB) * HD + d;
            *(float2*)pA = make_float2(acc[mb][nb][0] + bx, acc[mb][nb][1] + by);
            *(float2*)pB = make_float2(acc[mb][nb][2] + bx, acc[mb][nb][3] + by);
        }
    }
}

// ---------------------------------------------------------------------------
// Kernel 2: causal flash attention, fp32 SIMT (unchanged — passing at R1).
// ---------------------------------------------------------------------------
#define AQ 128
#define AK 64

__global__ __launch_bounds__(128, 3) void attn_kernel(float* __restrict__ out)
{
    __shared__ float Ks[AK][HD];
    __shared__ float Vs[AK][HD];

    const int bh  = blockIdx.y;
    const int b   = bh / NHEAD;
    const int h   = bh % NHEAD;
    const int r0  = (gridDim.x - 1 - blockIdx.x) * AQ;
    const int row = r0 + threadIdx.x;

    const float* kbase = g_k + (size_t)bh * TLEN * HD;
    const float* vbase = g_v + (size_t)bh * TLEN * HD;

    float q[HD];
    {
        const float4* qp = (const float4*)(g_q + ((size_t)bh * TLEN + row) * HD);
#pragma unroll
        for (int d4 = 0; d4 < HD / 4; d4++) {
            float4 t = qp[d4];
            q[4 * d4 + 0] = t.x * QK_SCALE;
            q[4 * d4 + 1] = t.y * QK_SCALE;
            q[4 * d4 + 2] = t.z * QK_SCALE;
            q[4 * d4 + 3] = t.w * QK_SCALE;
        }
    }

    float o[HD];
#pragma unroll
    for (int d = 0; d < HD; d++) o[d] = 0.f;
    float m = -INFINITY;
    float l = 0.f;

    const int nkt = r0 / AK + 2;

    for (int kt = 0; kt < nkt; kt++) {
        __syncthreads();
        {
            const float4* srcK = (const float4*)(kbase + (size_t)kt * AK * HD);
            const float4* srcV = (const float4*)(vbase + (size_t)kt * AK * HD);
            float4* dK = (float4*)&Ks[0][0];
            float4* dV = (float4*)&Vs[0][0];
#pragma unroll
            for (int i = 0; i < (AK * HD / 4) / AQ; i++) {
                const int idx = threadIdx.x + i * AQ;
                dK[idx] = srcK[idx];
                dV[idx] = srcV[idx];
            }
        }
        __syncthreads();

        const int ktbase = kt * AK;
#pragma unroll 1
        for (int j = 0; j < AK; j++) {
            const int jj = ktbase + j;
            if (jj > row) break;

            const float4* kr = (const float4*)Ks[j];
            float s0 = 0.f, s1 = 0.f, s2 = 0.f, s3 = 0.f;
#pragma unroll
            for (int d4 = 0; d4 < HD / 4; d4++) {
                float4 kv = kr[d4];
                s0 = fmaf(q[4 * d4 + 0], kv.x, s0);
                s1 = fmaf(q[4 * d4 + 1], kv.y, s1);
                s2 = fmaf(q[4 * d4 + 2], kv.z, s2);
                s3 = fmaf(q[4 * d4 + 3], kv.w, s3);
            }
            const float s = (s0 + s1) + (s2 + s3);

            if (s > m) {
                const float cc = __expf(m - s);
                l *= cc;
#pragma unroll
                for (int d = 0; d < HD; d++) o[d] *= cc;
                m = s;
            }
            const float p = __expf(s - m);
            l += p;

            const float4* vr = (const float4*)Vs[j];
#pragma unroll
            for (int d4 = 0; d4 < HD / 4; d4++) {
                float4 vv = vr[d4];
                o[4 * d4 + 0] = fmaf(p, vv.x, o[4 * d4 + 0]);
                o[4 * d4 + 1] = fmaf(p, vv.y, o[4 * d4 + 1]);
                o[4 * d4 + 2] = fmaf(p, vv.z, o[4 * d4 + 2]);
                o[4 * d4 + 3] = fmaf(p, vv.w, o[4 * d4 + 3]);
            }
        }
    }

    const float inv = 1.f / l;
    float4* op = (float4*)(out + ((size_t)b * TLEN + row) * CDIM + h * HD);
#pragma unroll
    for (int d4 = 0; d4 < HD / 4; d4++) {
        float4 v;
        v.x = o[4 * d4 + 0] * inv;
        v.y = o[4 * d4 + 1] * inv;
        v.z = o[4 * d4 + 2] * inv;
        v.w = o[4 * d4 + 3] * inv;
        op[d4] = v;
    }
}

// ---------------------------------------------------------------------------
extern "C" void kernel_launch(void* const* d_in, const int* in_sizes, int n_in,
                              void* d_out, int out_size)
{
    const float* x    = (const float*)d_in[0];   // [4, 2048, 1024]
    const float* w    = (const float*)d_in[1];   // [3072, 1024]
    const float* bias = (const float*)d_in[2];   // [3072]
    float* out        = (float*)d_out;           // [4, 2048, 1024]

    (void)in_sizes; (void)n_in; (void)out_size;

    cudaFuncSetAttribute(qkv_mma_kernel,
                         cudaFuncAttributeMaxDynamicSharedMemorySize, DYN_SMEM);

    dim3 ggrid(3 * CDIM / TN, (BSZ * TLEN) / TM);   // (24, 64)
    qkv_mma_kernel<<<ggrid, 256, DYN_SMEM>>>(x, w, bias);

    dim3 agrid(TLEN / AQ, BSZ * NHEAD);             // (16, 64)
    attn_kernel<<<agrid, 128>>>(out);
}

// round 4
// speedup vs baseline: 4.1407x; 2.6216x over previous
#include <cuda_runtime.h>
#include <math.h>
#include <stdint.h>

#define BSZ   4
#define TLEN  2048
#define CDIM  1024
#define NHEAD 16
#define HD    64

#define SCRATCH_ELEMS (BSZ * NHEAD * TLEN * HD)   // 8,388,608 floats = 32 MB each

__device__ float g_q[SCRATCH_ELEMS];
__device__ float g_k[SCRATCH_ELEMS];
__device__ float g_v[SCRATCH_ELEMS];

// ===========================================================================
// Helpers — baseline-ISA only (cp.async + mma.sync; NO tcgen05 on sm_100)
// ===========================================================================
__device__ __forceinline__ uint32_t smem_u32(const void* p) {
    uint32_t a;
    asm("{ .reg .u64 t; cvta.to.shared.u64 t, %1; cvt.u32.u64 %0, t; }"
        : "=r"(a) : "l"(p));
    return a;
}

__device__ __forceinline__ void cp_async16(uint32_t saddr, const void* gaddr) {
    asm volatile("cp.async.cg.shared.global [%0], [%1], 16;"
                 :: "r"(saddr), "l"(gaddr) : "memory");
}
__device__ __forceinline__ void cp_async_commit() {
    asm volatile("cp.async.commit_group;" ::: "memory");
}
template <int N>
__device__ __forceinline__ void cp_async_wait() {
    asm volatile("cp.async.wait_group %0;" :: "n"(N) : "memory");
}

__device__ __forceinline__ uint32_t f32_to_tf32(float f) {
    uint32_t r;
    asm("cvt.rna.tf32.f32 %0, %1;" : "=r"(r) : "f"(f));
    return r;
}

__device__ __forceinline__ float ex2f(float x) {
    float y;
    asm("ex2.approx.ftz.f32 %0, %1;" : "=f"(y) : "f"(x));
    return y;
}

// D += A(16x8 row) * B(8x8 col), tf32 inputs, f32 accumulate
__device__ __forceinline__ void mma_16n8k8_tf32(
    float* d, uint32_t a0, uint32_t a1, uint32_t a2, uint32_t a3,
    uint32_t b0, uint32_t b1)
{
    asm volatile(
        "mma.sync.aligned.m16n8k8.row.col.f32.tf32.tf32.f32 "
        "{%0,%1,%2,%3}, {%4,%5,%6,%7}, {%8,%9}, {%0,%1,%2,%3};"
        : "+f"(d[0]), "+f"(d[1]), "+f"(d[2]), "+f"(d[3])
        : "r"(a0), "r"(a1), "r"(a2), "r"(a3), "r"(b0), "r"(b1));
}

// ===========================================================================
// Kernel 1: QKV projection via mma.sync tf32  (unchanged from R3, passing)
// ===========================================================================
#define TM 128
#define TN 128
#define NSTG 3
#define LDP 36
#define A_STG_FLTS (TM * LDP)
#define B_STG_FLTS (TN * LDP)
#define STG_FLTS   (A_STG_FLTS + B_STG_FLTS)
#define NCHUNK (CDIM / 32)
#define DYN_SMEM (NSTG * STG_FLTS * 4)

__global__ void __launch_bounds__(256, 2) qkv_mma_kernel(
    const float* __restrict__ x,
    const float* __restrict__ w,
    const float* __restrict__ bias)
{
    extern __shared__ float smem[];

    const int tid = threadIdx.x;
    const int wid = tid >> 5;
    const int lid = tid & 31;
    const int g   = lid >> 2;
    const int c   = lid & 3;
    const int warp_m = (wid & 3) * 32;
    const int warp_n = (wid >> 2) * 64;
    const int m0  = blockIdx.y * TM;
    const int n0  = blockIdx.x * TN;

    const uint32_t sbase = smem_u32(smem);

    const char* gptr[8];
    uint32_t    soff[8];
#pragma unroll
    for (int t = 0; t < 8; t++) {
        const int cc = tid + t * 256;
        if (cc < 1024) {
            const int row = cc >> 3, o = cc & 7;
            gptr[t] = (const char*)(x + (size_t)(m0 + row) * CDIM) + o * 16;
            soff[t] = (uint32_t)(row * LDP * 4 + o * 16);
        } else {
            const int cb = cc - 1024;
            const int row = cb >> 3, o = cb & 7;
            gptr[t] = (const char*)(w + (size_t)(n0 + row) * CDIM) + o * 16;
            soff[t] = (uint32_t)(A_STG_FLTS * 4 + row * LDP * 4 + o * 16);
        }
    }

#define LOAD_STAGE(chunk)                                                   \
    do {                                                                    \
        const uint32_t sb_ = sbase + ((chunk) % NSTG) * (STG_FLTS * 4);     \
        const int gof_ = (chunk) * 128;                                     \
        _Pragma("unroll")                                                   \
        for (int t = 0; t < 8; t++)                                         \
            cp_async16(sb_ + soff[t], gptr[t] + gof_);                      \
        cp_async_commit();                                                  \
    } while (0)

    float acc[2][8][4];
#pragma unroll
    for (int mb = 0; mb < 2; mb++)
#pragma unroll
        for (int nb = 0; nb < 8; nb++)
#pragma unroll
            for (int r = 0; r < 4; r++) acc[mb][nb][r] = 0.f;

    LOAD_STAGE(0);
    LOAD_STAGE(1);

    for (int i = 0; i < NCHUNK; i++) {
        cp_async_wait<NSTG - 2>();
        __syncthreads();

        if (i + 2 < NCHUNK) { LOAD_STAGE(i + 2); }
        else                { cp_async_commit(); }

        const float* As = smem + (i % NSTG) * STG_FLTS;
        const float* Bs = As + A_STG_FLTS;

#pragma unroll
        for (int ks = 0; ks < 4; ks++) {
            const int k = ks * 8;
            uint32_t af[2][4];
#pragma unroll
            for (int mb = 0; mb < 2; mb++) {
                const float* ap = As + (warp_m + mb * 16 + g) * LDP + k + c;
                af[mb][0] = f32_to_tf32(ap[0]);
                af[mb][1] = f32_to_tf32(ap[8 * LDP]);
                af[mb][2] = f32_to_tf32(ap[4]);
                af[mb][3] = f32_to_tf32(ap[8 * LDP + 4]);
            }
            uint32_t bf[8][2];
#pragma unroll
            for (int nb = 0; nb < 8; nb++) {
                const float* bp = Bs + (warp_n + nb * 8 + g) * LDP + k + c;
                bf[nb][0] = f32_to_tf32(bp[0]);
                bf[nb][1] = f32_to_tf32(bp[4]);
            }
#pragma unroll
            for (int mb = 0; mb < 2; mb++)
#pragma unroll
                for (int nb = 0; nb < 8; nb++)
                    mma_16n8k8_tf32(acc[mb][nb],
                                    af[mb][0], af[mb][1], af[mb][2], af[mb][3],
                                    bf[nb][0], bf[nb][1]);
        }
        __syncthreads();
    }

    const int which = n0 >> 10;
    float* dst = (which == 0) ? g_q : (which == 1) ? g_k : g_v;

#pragma unroll
    for (int mb = 0; mb < 2; mb++) {
        const int mA = m0 + warp_m + mb * 16 + g;
        const int mB = mA + 8;
        const int bA = mA >> 11, tA = mA & (TLEN - 1);
        const int bB = mB >> 11, tB = mB & (TLEN - 1);
#pragma unroll
        for (int nb = 0; nb < 8; nb++) {
            const int n = n0 + warp_n + nb * 8 + 2 * c;
            const int h = (n >> 6) & (NHEAD - 1);
            const int d = n & 63;
            const float bx = __ldg(bias + n);
            const float by = __ldg(bias + n + 1);
            float* pA = dst + (((size_t)(bA * NHEAD + h) * TLEN) + tA) * HD + d;
            float* pB = dst + (((size_t)(bB * NHEAD + h) * TLEN) + tB) * HD + d;
            *(float2*)pA = make_float2(acc[mb][nb][0] + bx, acc[mb][nb][1] + by);
            *(float2*)pB = make_float2(acc[mb][nb][2] + bx, acc[mb][nb][3] + by);
        }
    }
}

// ===========================================================================
// Kernel 2: tensor-core causal flash attention (mma.sync tf32).
//   CTA = 8 warps, 128 q rows of one (b,h); warp tile = 16 q rows.
//   K/V tiles of 64 keys in smem, double-buffered cp.async, stride 68 floats
//   (conflict-free for both fragment patterns). Base-2 online softmax.
// ===========================================================================
#define ATM 128
#define ATK 64
#define VSTR 68                            // padded row stride (floats)
#define TILE_FLTS (ATK * VSTR)             // 4352
#define ABUF_FLTS (2 * TILE_FLTS)          // K + V per buffer
#define ATTN_SMEM (2 * ABUF_FLTS * 4)      // 69632 B

__global__ void __launch_bounds__(256, 1) attn_tc_kernel(float* __restrict__ out)
{
    extern __shared__ float sm[];

    const int tid  = threadIdx.x;
    const int wid  = tid >> 5;
    const int lane = tid & 31;
    const int g    = lane >> 2;
    const int c    = lane & 3;
    const int bh   = blockIdx.y;
    const int b    = bh >> 4;
    const int h    = bh & (NHEAD - 1);
    const int q0   = (gridDim.x - 1 - blockIdx.x) * ATM;   // heavy tiles first
    const int r0   = q0 + wid * 16 + g;
    const int r1   = r0 + 8;

    const float* qb = g_q + (size_t)bh * TLEN * HD;
    const float* kb = g_k + (size_t)bh * TLEN * HD;
    const float* vb = g_v + (size_t)bh * TLEN * HD;

    // ---- Q fragments, scale*log2e folded in, converted to tf32 once ----
    const float QS = 0.125f * 1.44269504f;
    uint32_t qa[8][4];
#pragma unroll
    for (int ks = 0; ks < 8; ks++) {
        const int k = ks * 8;
        qa[ks][0] = f32_to_tf32(qb[(size_t)r0 * HD + k + c]     * QS);
        qa[ks][1] = f32_to_tf32(qb[(size_t)r1 * HD + k + c]     * QS);
        qa[ks][2] = f32_to_tf32(qb[(size_t)r0 * HD + k + c + 4] * QS);
        qa[ks][3] = f32_to_tf32(qb[(size_t)r1 * HD + k + c + 4] * QS);
    }

    float o[8][4];
#pragma unroll
    for (int nb = 0; nb < 8; nb++)
#pragma unroll
        for (int r = 0; r < 4; r++) o[nb][r] = 0.f;
    float mrow0 = -1e30f, mrow1 = -1e30f;
    float lrow0 = 0.f,    lrow1 = 0.f;

    const int nkt = q0 / ATK + 2;

    // ---- cp.async tile loader: 2048 x 16B chunks, 8 per thread ----
#define ATTN_LOAD(kt)                                                        \
    do {                                                                     \
        const float* ksrc_ = kb + (size_t)(kt) * ATK * HD;                   \
        const float* vsrc_ = vb + (size_t)(kt) * ATK * HD;                   \
        const uint32_t sd_ = smem_u32(sm) + ((kt) & 1) * (ABUF_FLTS * 4);    \
        _Pragma("unroll")                                                    \
        for (int i_ = 0; i_ < 8; i_++) {                                     \
            const int id_  = tid + i_ * 256;                                 \
            const int row_ = (id_ >> 4) & 63;                                \
            const int o4_  = id_ & 15;                                       \
            const bool isK_ = id_ < 1024;                                    \
            const float* src_ = (isK_ ? ksrc_ : vsrc_) + row_ * HD + o4_ * 4;\
            const uint32_t dst_ = sd_ + (isK_ ? 0 : TILE_FLTS * 4)           \
                                + (uint32_t)(row_ * VSTR + o4_ * 4) * 4;     \
            cp_async16(dst_, src_);                                          \
        }                                                                    \
        cp_async_commit();                                                   \
    } while (0)

    ATTN_LOAD(0);

    for (int kt = 0; kt < nkt; kt++) {
        if (kt + 1 < nkt) { ATTN_LOAD(kt + 1); cp_async_wait<1>(); }
        else              { cp_async_wait<0>(); }
        __syncthreads();

        // warp fully masked for this tile? (only possible on last tile)
        const bool active = (kt * ATK) <= (q0 + wid * 16 + 15);
        if (active) {
            const float* SK = sm + (kt & 1) * ABUF_FLTS;
            const float* SV = SK + TILE_FLTS;

            // ---- S = Q K^T (16 x 64) ----
            float s[8][4];
#pragma unroll
            for (int nb = 0; nb < 8; nb++)
#pragma unroll
                for (int r = 0; r < 4; r++) s[nb][r] = 0.f;

#pragma unroll
            for (int ks = 0; ks < 8; ks++) {
                const int k = ks * 8;
#pragma unroll
                for (int nb = 0; nb < 8; nb++) {
                    const float* kp = SK + (nb * 8 + g) * VSTR + k + c;
                    const uint32_t b0 = f32_to_tf32(kp[0]);
                    const uint32_t b1 = f32_to_tf32(kp[4]);
                    mma_16n8k8_tf32(s[nb], qa[ks][0], qa[ks][1],
                                    qa[ks][2], qa[ks][3], b0, b1);
                }
            }

            // ---- causal mask (last two tiles only) ----
            if (kt >= nkt - 2) {
                const int j0 = kt * ATK;
#pragma unroll
                for (int nb = 0; nb < 8; nb++) {
                    const int jA = j0 + nb * 8 + 2 * c;
                    if (jA     > r0) s[nb][0] = -1e30f;
                    if (jA + 1 > r0) s[nb][1] = -1e30f;
                    if (jA     > r1) s[nb][2] = -1e30f;
                    if (jA + 1 > r1) s[nb][3] = -1e30f;
                }
            }

            // ---- online softmax (tile-level, base 2) ----
            float t0 = -1e30f, t1 = -1e30f;
#pragma unroll
            for (int nb = 0; nb < 8; nb++) {
                t0 = fmaxf(t0, fmaxf(s[nb][0], s[nb][1]));
                t1 = fmaxf(t1, fmaxf(s[nb][2], s[nb][3]));
            }
            t0 = fmaxf(t0, __shfl_xor_sync(0xffffffffu, t0, 1));
            t0 = fmaxf(t0, __shfl_xor_sync(0xffffffffu, t0, 2));
            t1 = fmaxf(t1, __shfl_xor_sync(0xffffffffu, t1, 1));
            t1 = fmaxf(t1, __shfl_xor_sync(0xffffffffu, t1, 2));

            const float mn0 = fmaxf(mrow0, t0);
            const float mn1 = fmaxf(mrow1, t1);
            const float a0 = ex2f(mrow0 - mn0);
            const float a1 = ex2f(mrow1 - mn1);
            mrow0 = mn0; mrow1 = mn1;
            lrow0 *= a0; lrow1 *= a1;
#pragma unroll
            for (int nb = 0; nb < 8; nb++) {
                o[nb][0] *= a0; o[nb][1] *= a0;
                o[nb][2] *= a1; o[nb][3] *= a1;
            }

            // p = exp2(s - m); accumulate l; store tf32 bits back into s
#pragma unroll
            for (int nb = 0; nb < 8; nb++) {
                const float p0 = ex2f(s[nb][0] - mn0);
                const float p1 = ex2f(s[nb][1] - mn0);
                const float p2 = ex2f(s[nb][2] - mn1);
                const float p3 = ex2f(s[nb][3] - mn1);
                lrow0 += p0 + p1;
                lrow1 += p2 + p3;
                s[nb][0] = __uint_as_float(f32_to_tf32(p0));
                s[nb][1] = __uint_as_float(f32_to_tf32(p1));
                s[nb][2] = __uint_as_float(f32_to_tf32(p2));
                s[nb][3] = __uint_as_float(f32_to_tf32(p3));
            }

            // ---- O += P V  (V rows permuted: k-slot c <- key 2c, c+4 <- 2c+1) ----
#pragma unroll
            for (int kbk = 0; kbk < 8; kbk++) {
                const uint32_t pa0 = __float_as_uint(s[kbk][0]);
                const uint32_t pa1 = __float_as_uint(s[kbk][2]);
                const uint32_t pa2 = __float_as_uint(s[kbk][1]);
                const uint32_t pa3 = __float_as_uint(s[kbk][3]);
                const float* vr0 = SV + (kbk * 8 + 2 * c)     * VSTR + g;
                const float* vr1 = SV + (kbk * 8 + 2 * c + 1) * VSTR + g;
#pragma unroll
                for (int nb = 0; nb < 8; nb++) {
                    const uint32_t b0 = f32_to_tf32(vr0[nb * 8]);
                    const uint32_t b1 = f32_to_tf32(vr1[nb * 8]);
                    mma_16n8k8_tf32(o[nb], pa0, pa1, pa2, pa3, b0, b1);
                }
            }
        }
        __syncthreads();   // all warps done reading before buffer is reloaded
    }

    // ---- finalize: reduce l across quad, normalize, store ----
    lrow0 += __shfl_xor_sync(0xffffffffu, lrow0, 1);
    lrow0 += __shfl_xor_sync(0xffffffffu, lrow0, 2);
    lrow1 += __shfl_xor_sync(0xffffffffu, lrow1, 1);
    lrow1 += __shfl_xor_sync(0xffffffffu, lrow1, 2);
    const float inv0 = 1.f / lrow0;
    const float inv1 = 1.f / lrow1;

    float* orow0 = out + ((size_t)b * TLEN + r0) * CDIM + h * HD;
    float* orow1 = out + ((size_t)b * TLEN + r1) * CDIM + h * HD;
#pragma unroll
    for (int nb = 0; nb < 8; nb++) {
        const int d = nb * 8 + 2 * c;
        *(float2*)(orow0 + d) = make_float2(o[nb][0] * inv0, o[nb][1] * inv0);
        *(float2*)(orow1 + d) = make_float2(o[nb][2] * inv1, o[nb][3] * inv1);
    }
}

// ---------------------------------------------------------------------------
extern "C" void kernel_launch(void* const* d_in, const int* in_sizes, int n_in,
                              void* d_out, int out_size)
{
    const float* x    = (const float*)d_in[0];   // [4, 2048, 1024]
    const float* w    = (const float*)d_in[1];   // [3072, 1024]
    const float* bias = (const float*)d_in[2];   // [3072]
    float* out        = (float*)d_out;           // [4, 2048, 1024]

    (void)in_sizes; (void)n_in; (void)out_size;

    cudaFuncSetAttribute(qkv_mma_kernel,
                         cudaFuncAttributeMaxDynamicSharedMemorySize, DYN_SMEM);
    cudaFuncSetAttribute(attn_tc_kernel,
                         cudaFuncAttributeMaxDynamicSharedMemorySize, ATTN_SMEM);

    dim3 ggrid(3 * CDIM / TN, (BSZ * TLEN) / TM);   // (24, 64)
    qkv_mma_kernel<<<ggrid, 256, DYN_SMEM>>>(x, w, bias);

    dim3 agrid(TLEN / ATM, BSZ * NHEAD);            // (16, 64)
    attn_tc_kernel<<<agrid, 256, ATTN_SMEM>>>(out);
}

// round 5
// speedup vs baseline: 4.7362x; 1.1438x over previous
#include <cuda_runtime.h>
#include <math.h>
#include <stdint.h>

#define BSZ   4
#define TLEN  2048
#define CDIM  1024
#define NHEAD 16
#define HD    64

#define SCRATCH_ELEMS (BSZ * NHEAD * TLEN * HD)   // 8,388,608 floats
#define XN (BSZ * TLEN * CDIM)                    // 8,388,608
#define WN (3 * CDIM * CDIM)                      // 3,145,728

__device__ float g_q[SCRATCH_ELEMS];   // tf32 bits, Q pre-scaled by 0.125*log2e
__device__ float g_k[SCRATCH_ELEMS];   // tf32 bits
__device__ float g_v[SCRATCH_ELEMS];   // tf32 bits
__device__ float g_xt[XN];             // x  as tf32 bits
__device__ float g_wt[WN];             // W  as tf32 bits

// ===========================================================================
// Helpers — baseline-ISA only (cp.async + mma.sync; NO tcgen05 on sm_100)
// ===========================================================================
__device__ __forceinline__ uint32_t smem_u32(const void* p) {
    uint32_t a;
    asm("{ .reg .u64 t; cvta.to.shared.u64 t, %1; cvt.u32.u64 %0, t; }"
        : "=r"(a) : "l"(p));
    return a;
}

__device__ __forceinline__ void cp_async16(uint32_t saddr, const void* gaddr) {
    asm volatile("cp.async.cg.shared.global [%0], [%1], 16;"
                 :: "r"(saddr), "l"(gaddr) : "memory");
}
__device__ __forceinline__ void cp_async_commit() {
    asm volatile("cp.async.commit_group;" ::: "memory");
}
template <int N>
__device__ __forceinline__ void cp_async_wait() {
    asm volatile("cp.async.wait_group %0;" :: "n"(N) : "memory");
}

__device__ __forceinline__ uint32_t f32_to_tf32(float f) {
    uint32_t r;
    asm("cvt.rna.tf32.f32 %0, %1;" : "=r"(r) : "f"(f));
    return r;
}

__device__ __forceinline__ float ex2f(float x) {
    float y;
    asm("ex2.approx.ftz.f32 %0, %1;" : "=f"(y) : "f"(x));
    return y;
}

// D += A(16x8 row) * B(8x8 col), tf32 inputs, f32 accumulate
__device__ __forceinline__ void mma_16n8k8_tf32(
    float* d, uint32_t a0, uint32_t a1, uint32_t a2, uint32_t a3,
    uint32_t b0, uint32_t b1)
{
    asm volatile(
        "mma.sync.aligned.m16n8k8.row.col.f32.tf32.tf32.f32 "
        "{%0,%1,%2,%3}, {%4,%5,%6,%7}, {%8,%9}, {%0,%1,%2,%3};"
        : "+f"(d[0]), "+f"(d[1]), "+f"(d[2]), "+f"(d[3])
        : "r"(a0), "r"(a1), "r"(a2), "r"(a3), "r"(b0), "r"(b1));
}

// ===========================================================================
// Kernel 0: convert x and W to tf32 bit patterns (vectorized, grid-stride)
// ===========================================================================
__global__ void __launch_bounds__(256) tf32_convert_kernel(
    const float* __restrict__ x, const float* __restrict__ w)
{
    const int nx4 = XN / 4;
    const int nw4 = WN / 4;
    const int stride = gridDim.x * blockDim.x;
    for (int i = blockIdx.x * blockDim.x + threadIdx.x; i < nx4 + nw4; i += stride) {
        float4 v;
        float4* dst;
        if (i < nx4) { v = ((const float4*)x)[i]; dst = (float4*)g_xt + i; }
        else         { v = ((const float4*)w)[i - nx4]; dst = (float4*)g_wt + (i - nx4); }
        float4 o;
        o.x = __uint_as_float(f32_to_tf32(v.x));
        o.y = __uint_as_float(f32_to_tf32(v.y));
        o.z = __uint_as_float(f32_to_tf32(v.z));
        o.w = __uint_as_float(f32_to_tf32(v.w));
        *dst = o;
    }
}

// ===========================================================================
// Kernel 1: QKV projection via mma.sync tf32 — inputs pre-converted,
//           epilogue stores tf32-rounded Q/K/V (Q pre-scaled).
// ===========================================================================
#define TM 128
#define TN 128
#define NSTG 3
#define LDP 36
#define A_STG_FLTS (TM * LDP)
#define B_STG_FLTS (TN * LDP)
#define STG_FLTS   (A_STG_FLTS + B_STG_FLTS)
#define NCHUNK (CDIM / 32)
#define DYN_SMEM (NSTG * STG_FLTS * 4)
#define Q_PRESCALE (0.125f * 1.44269504f)   // 1/sqrt(64) * log2(e)

__global__ void __launch_bounds__(256, 2) qkv_mma_kernel(
    const float* __restrict__ bias)
{
    extern __shared__ float smem[];

    const int tid = threadIdx.x;
    const int wid = tid >> 5;
    const int lid = tid & 31;
    const int g   = lid >> 2;
    const int c   = lid & 3;
    const int warp_m = (wid & 3) * 32;
    const int warp_n = (wid >> 2) * 64;
    const int m0  = blockIdx.y * TM;
    const int n0  = blockIdx.x * TN;

    const uint32_t sbase = smem_u32(smem);

    const char* gptr[8];
    uint32_t    soff[8];
#pragma unroll
    for (int t = 0; t < 8; t++) {
        const int cc = tid + t * 256;
        if (cc < 1024) {
            const int row = cc >> 3, o = cc & 7;
            gptr[t] = (const char*)(g_xt + (size_t)(m0 + row) * CDIM) + o * 16;
            soff[t] = (uint32_t)(row * LDP * 4 + o * 16);
        } else {
            const int cb = cc - 1024;
            const int row = cb >> 3, o = cb & 7;
            gptr[t] = (const char*)(g_wt + (size_t)(n0 + row) * CDIM) + o * 16;
            soff[t] = (uint32_t)(A_STG_FLTS * 4 + row * LDP * 4 + o * 16);
        }
    }

#define LOAD_STAGE(chunk)                                                   \
    do {                                                                    \
        const uint32_t sb_ = sbase + ((chunk) % NSTG) * (STG_FLTS * 4);     \
        const int gof_ = (chunk) * 128;                                     \
        _Pragma("unroll")                                                   \
        for (int t = 0; t < 8; t++)                                         \
            cp_async16(sb_ + soff[t], gptr[t] + gof_);                      \
        cp_async_commit();                                                  \
    } while (0)

    float acc[2][8][4];
#pragma unroll
    for (int mb = 0; mb < 2; mb++)
#pragma unroll
        for (int nb = 0; nb < 8; nb++)
#pragma unroll
            for (int r = 0; r < 4; r++) acc[mb][nb][r] = 0.f;

    LOAD_STAGE(0);
    LOAD_STAGE(1);

    for (int i = 0; i < NCHUNK; i++) {
        cp_async_wait<NSTG - 2>();
        __syncthreads();

        if (i + 2 < NCHUNK) { LOAD_STAGE(i + 2); }
        else                { cp_async_commit(); }

        const uint32_t* As = (const uint32_t*)(smem + (i % NSTG) * STG_FLTS);
        const uint32_t* Bs = As + A_STG_FLTS;

#pragma unroll
        for (int ks = 0; ks < 4; ks++) {
            const int k = ks * 8;
            uint32_t af[2][4];
#pragma unroll
            for (int mb = 0; mb < 2; mb++) {
                const uint32_t* ap = As + (warp_m + mb * 16 + g) * LDP + k + c;
                af[mb][0] = ap[0];
                af[mb][1] = ap[8 * LDP];
                af[mb][2] = ap[4];
                af[mb][3] = ap[8 * LDP + 4];
            }
            uint32_t bf[8][2];
#pragma unroll
            for (int nb = 0; nb < 8; nb++) {
                const uint32_t* bp = Bs + (warp_n + nb * 8 + g) * LDP + k + c;
                bf[nb][0] = bp[0];
                bf[nb][1] = bp[4];
            }
#pragma unroll
            for (int mb = 0; mb < 2; mb++)
#pragma unroll
                for (int nb = 0; nb < 8; nb++)
                    mma_16n8k8_tf32(acc[mb][nb],
                                    af[mb][0], af[mb][1], af[mb][2], af[mb][3],
                                    bf[nb][0], bf[nb][1]);
        }
        __syncthreads();
    }

    // ---- epilogue: bias (+ Q prescale), tf32-round, scatter to [B,H,T,64] ----
    const int which = n0 >> 10;
    float* dst = (which == 0) ? g_q : (which == 1) ? g_k : g_v;
    const float sc = (which == 0) ? Q_PRESCALE : 1.0f;

#pragma unroll
    for (int mb = 0; mb < 2; mb++) {
        const int mA = m0 + warp_m + mb * 16 + g;
        const int mB = mA + 8;
        const int bA = mA >> 11, tA = mA & (TLEN - 1);
        const int bB = mB >> 11, tB = mB & (TLEN - 1);
#pragma unroll
        for (int nb = 0; nb < 8; nb++) {
            const int n = n0 + warp_n + nb * 8 + 2 * c;
            const int h = (n >> 6) & (NHEAD - 1);
            const int d = n & 63;
            const float bx = __ldg(bias + n);
            const float by = __ldg(bias + n + 1);
            float* pA = dst + (((size_t)(bA * NHEAD + h) * TLEN) + tA) * HD + d;
            float* pB = dst + (((size_t)(bB * NHEAD + h) * TLEN) + tB) * HD + d;
            float2 vA, vB;
            vA.x = __uint_as_float(f32_to_tf32((acc[mb][nb][0] + bx) * sc));
            vA.y = __uint_as_float(f32_to_tf32((acc[mb][nb][1] + by) * sc));
            vB.x = __uint_as_float(f32_to_tf32((acc[mb][nb][2] + bx) * sc));
            vB.y = __uint_as_float(f32_to_tf32((acc[mb][nb][3] + by) * sc));
            *(float2*)pA = vA;
            *(float2*)pB = vB;
        }
    }
}

// ===========================================================================
// Kernel 2: tensor-core causal flash attention — K/V/Q already tf32 bits.
// ===========================================================================
#define ATM 128
#define ATK 64
#define VSTR 68
#define TILE_FLTS (ATK * VSTR)
#define ABUF_FLTS (2 * TILE_FLTS)
#define ATTN_SMEM (2 * ABUF_FLTS * 4)

__global__ void __launch_bounds__(256, 1) attn_tc_kernel(float* __restrict__ out)
{
    extern __shared__ float sm[];

    const int tid  = threadIdx.x;
    const int wid  = tid >> 5;
    const int lane = tid & 31;
    const int g    = lane >> 2;
    const int c    = lane & 3;
    const int bh   = blockIdx.y;
    const int b    = bh >> 4;
    const int h    = bh & (NHEAD - 1);
    const int q0   = (gridDim.x - 1 - blockIdx.x) * ATM;
    const int r0   = q0 + wid * 16 + g;
    const int r1   = r0 + 8;

    const float* qb = g_q + (size_t)bh * TLEN * HD;
    const float* kb = g_k + (size_t)bh * TLEN * HD;
    const float* vb = g_v + (size_t)bh * TLEN * HD;

    // Q fragments: already tf32 bits with softmax scale folded in
    uint32_t qa[8][4];
#pragma unroll
    for (int ks = 0; ks < 8; ks++) {
        const int k = ks * 8;
        qa[ks][0] = __float_as_uint(qb[(size_t)r0 * HD + k + c]);
        qa[ks][1] = __float_as_uint(qb[(size_t)r1 * HD + k + c]);
        qa[ks][2] = __float_as_uint(qb[(size_t)r0 * HD + k + c + 4]);
        qa[ks][3] = __float_as_uint(qb[(size_t)r1 * HD + k + c + 4]);
    }

    float o[8][4];
#pragma unroll
    for (int nb = 0; nb < 8; nb++)
#pragma unroll
        for (int r = 0; r < 4; r++) o[nb][r] = 0.f;
    float mrow0 = -1e30f, mrow1 = -1e30f;
    float lrow0 = 0.f,    lrow1 = 0.f;

    const int nkt = q0 / ATK + 2;

#define ATTN_LOAD(kt)                                                        \
    do {                                                                     \
        const float* ksrc_ = kb + (size_t)(kt) * ATK * HD;                   \
        const float* vsrc_ = vb + (size_t)(kt) * ATK * HD;                   \
        const uint32_t sd_ = smem_u32(sm) + ((kt) & 1) * (ABUF_FLTS * 4);    \
        _Pragma("unroll")                                                    \
        for (int i_ = 0; i_ < 8; i_++) {                                     \
            const int id_  = tid + i_ * 256;                                 \
            const int row_ = (id_ >> 4) & 63;                                \
            const int o4_  = id_ & 15;                                       \
            const bool isK_ = id_ < 1024;                                    \
            const float* src_ = (isK_ ? ksrc_ : vsrc_) + row_ * HD + o4_ * 4;\
            const uint32_t dst_ = sd_ + (isK_ ? 0 : TILE_FLTS * 4)           \
                                + (uint32_t)(row_ * VSTR + o4_ * 4) * 4;     \
            cp_async16(dst_, src_);                                          \
        }                                                                    \
        cp_async_commit();                                                   \
    } while (0)

    ATTN_LOAD(0);

    for (int kt = 0; kt < nkt; kt++) {
        if (kt + 1 < nkt) { ATTN_LOAD(kt + 1); cp_async_wait<1>(); }
        else              { cp_async_wait<0>(); }
        __syncthreads();

        const bool active = (kt * ATK) <= (q0 + wid * 16 + 15);
        if (active) {
            const uint32_t* SK = (const uint32_t*)(sm + (kt & 1) * ABUF_FLTS);
            const uint32_t* SV = SK + TILE_FLTS;

            // ---- S = Q K^T (16 x 64) ----
            float s[8][4];
#pragma unroll
            for (int nb = 0; nb < 8; nb++)
#pragma unroll
                for (int r = 0; r < 4; r++) s[nb][r] = 0.f;

#pragma unroll
            for (int ks = 0; ks < 8; ks++) {
                const int k = ks * 8;
#pragma unroll
                for (int nb = 0; nb < 8; nb++) {
                    const uint32_t* kp = SK + (nb * 8 + g) * VSTR + k + c;
                    mma_16n8k8_tf32(s[nb], qa[ks][0], qa[ks][1],
                                    qa[ks][2], qa[ks][3], kp[0], kp[4]);
                }
            }

            // ---- causal mask (last two tiles only) ----
            if (kt >= nkt - 2) {
                const int j0 = kt * ATK;
#pragma unroll
                for (int nb = 0; nb < 8; nb++) {
                    const int jA = j0 + nb * 8 + 2 * c;
                    if (jA     > r0) s[nb][0] = -1e30f;
                    if (jA + 1 > r0) s[nb][1] = -1e30f;
                    if (jA     > r1) s[nb][2] = -1e30f;
                    if (jA + 1 > r1) s[nb][3] = -1e30f;
                }
            }

            // ---- online softmax (tile-level, base 2) ----
            float t0 = -1e30f, t1 = -1e30f;
#pragma unroll
            for (int nb = 0; nb < 8; nb++) {
                t0 = fmaxf(t0, fmaxf(s[nb][0], s[nb][1]));
                t1 = fmaxf(t1, fmaxf(s[nb][2], s[nb][3]));
            }
            t0 = fmaxf(t0, __shfl_xor_sync(0xffffffffu, t0, 1));
            t0 = fmaxf(t0, __shfl_xor_sync(0xffffffffu, t0, 2));
            t1 = fmaxf(t1, __shfl_xor_sync(0xffffffffu, t1, 1));
            t1 = fmaxf(t1, __shfl_xor_sync(0xffffffffu, t1, 2));

            const float mn0 = fmaxf(mrow0, t0);
            const float mn1 = fmaxf(mrow1, t1);
            const float a0 = ex2f(mrow0 - mn0);
            const float a1 = ex2f(mrow1 - mn1);
            mrow0 = mn0; mrow1 = mn1;
            lrow0 *= a0; lrow1 *= a1;
#pragma unroll
            for (int nb = 0; nb < 8; nb++) {
                o[nb][0] *= a0; o[nb][1] *= a0;
                o[nb][2] *= a1; o[nb][3] *= a1;
            }

#pragma unroll
            for (int nb = 0; nb < 8; nb++) {
                const float p0 = ex2f(s[nb][0] - mn0);
                const float p1 = ex2f(s[nb][1] - mn0);
                const float p2 = ex2f(s[nb][2] - mn1);
                const float p3 = ex2f(s[nb][3] - mn1);
                lrow0 += p0 + p1;
                lrow1 += p2 + p3;
                s[nb][0] = __uint_as_float(f32_to_tf32(p0));
                s[nb][1] = __uint_as_float(f32_to_tf32(p1));
                s[nb][2] = __uint_as_float(f32_to_tf32(p2));
                s[nb][3] = __uint_as_float(f32_to_tf32(p3));
            }

            // ---- O += P V  (V rows permuted: k-slot c <- key 2c, c+4 <- 2c+1) ----
#pragma unroll
            for (int kbk = 0; kbk < 8; kbk++) {
                const uint32_t pa0 = __float_as_uint(s[kbk][0]);
                const uint32_t pa1 = __float_as_uint(s[kbk][2]);
                const uint32_t pa2 = __float_as_uint(s[kbk][1]);
                const uint32_t pa3 = __float_as_uint(s[kbk][3]);
                const uint32_t* vr0 = SV + (kbk * 8 + 2 * c)     * VSTR + g;
                const uint32_t* vr1 = SV + (kbk * 8 + 2 * c + 1) * VSTR + g;
#pragma unroll
                for (int nb = 0; nb < 8; nb++) {
                    mma_16n8k8_tf32(o[nb], pa0, pa1, pa2, pa3,
                                    vr0[nb * 8], vr1[nb * 8]);
                }
            }
        }
        __syncthreads();
    }

    // ---- finalize ----
    lrow0 += __shfl_xor_sync(0xffffffffu, lrow0, 1);
    lrow0 += __shfl_xor_sync(0xffffffffu, lrow0, 2);
    lrow1 += __shfl_xor_sync(0xffffffffu, lrow1, 1);
    lrow1 += __shfl_xor_sync(0xffffffffu, lrow1, 2);
    const float inv0 = 1.f / lrow0;
    const float inv1 = 1.f / lrow1;

    float* orow0 = out + ((size_t)b * TLEN + r0) * CDIM + h * HD;
    float* orow1 = out + ((size_t)b * TLEN + r1) * CDIM + h * HD;
#pragma unroll
    for (int nb = 0; nb < 8; nb++) {
        const int d = nb * 8 + 2 * c;
        *(float2*)(orow0 + d) = make_float2(o[nb][0] * inv0, o[nb][1] * inv0);
        *(float2*)(orow1 + d) = make_float2(o[nb][2] * inv1, o[nb][3] * inv1);
    }
}

// ---------------------------------------------------------------------------
extern "C" void kernel_launch(void* const* d_in, const int* in_sizes, int n_in,
                              void* d_out, int out_size)
{
    const float* x    = (const float*)d_in[0];   // [4, 2048, 1024]
    const float* w    = (const float*)d_in[1];   // [3072, 1024]
    const float* bias = (const float*)d_in[2];   // [3072]
    float* out        = (float*)d_out;           // [4, 2048, 1024]

    (void)in_sizes; (void)n_in; (void)out_size;

    cudaFuncSetAttribute(qkv_mma_kernel,
                         cudaFuncAttributeMaxDynamicSharedMemorySize, DYN_SMEM);
    cudaFuncSetAttribute(attn_tc_kernel,
                         cudaFuncAttributeMaxDynamicSharedMemorySize, ATTN_SMEM);

    tf32_convert_kernel<<<1184, 256>>>(x, w);

    dim3 ggrid(3 * CDIM / TN, (BSZ * TLEN) / TM);   // (24, 64)
    qkv_mma_kernel<<<ggrid, 256, DYN_SMEM>>>(bias);

    dim3 agrid(TLEN / ATM, BSZ * NHEAD);            // (16, 64)
    attn_tc_kernel<<<agrid, 256, ATTN_SMEM>>>(out);
}

// round 6
// speedup vs baseline: 4.8092x; 1.0154x over previous
#include <cuda_runtime.h>
#include <math.h>
#include <stdint.h>

#define BSZ   4
#define TLEN  2048
#define CDIM  1024
#define NHEAD 16
#define HD    64

#define SCRATCH_ELEMS (BSZ * NHEAD * TLEN * HD)   // 8,388,608 floats
#define XN (BSZ * TLEN * CDIM)
#define WN (3 * CDIM * CDIM)

// g_q, g_k: [bh, t, d] with d PAIR-INTERLEAVED per 8-block, tf32 bits,
//           Q pre-scaled by 0.125*log2e.
// g_v:      TRANSPOSED [bh, d, t], natural d order, tf32 bits.
__device__ float g_q[SCRATCH_ELEMS];
__device__ float g_k[SCRATCH_ELEMS];
__device__ float g_v[SCRATCH_ELEMS];
__device__ float g_xt[XN];
__device__ float g_wt[WN];

// ===========================================================================
// Helpers
// ===========================================================================
__device__ __forceinline__ uint32_t smem_u32(const void* p) {
    uint32_t a;
    asm("{ .reg .u64 t; cvta.to.shared.u64 t, %1; cvt.u32.u64 %0, t; }"
        : "=r"(a) : "l"(p));
    return a;
}

__device__ __forceinline__ void cp_async16(uint32_t saddr, const void* gaddr) {
    asm volatile("cp.async.cg.shared.global [%0], [%1], 16;"
                 :: "r"(saddr), "l"(gaddr) : "memory");
}
__device__ __forceinline__ void cp_async_commit() {
    asm volatile("cp.async.commit_group;" ::: "memory");
}
template <int N>
__device__ __forceinline__ void cp_async_wait() {
    asm volatile("cp.async.wait_group %0;" :: "n"(N) : "memory");
}

__device__ __forceinline__ uint32_t f32_to_tf32(float f) {
    uint32_t r;
    asm("cvt.rna.tf32.f32 %0, %1;" : "=r"(r) : "f"(f));
    return r;
}

__device__ __forceinline__ float ex2f(float x) {
    float y;
    asm("ex2.approx.ftz.f32 %0, %1;" : "=f"(y) : "f"(x));
    return y;
}

__device__ __forceinline__ void mma_16n8k8_tf32(
    float* d, uint32_t a0, uint32_t a1, uint32_t a2, uint32_t a3,
    uint32_t b0, uint32_t b1)
{
    asm volatile(
        "mma.sync.aligned.m16n8k8.row.col.f32.tf32.tf32.f32 "
        "{%0,%1,%2,%3}, {%4,%5,%6,%7}, {%8,%9}, {%0,%1,%2,%3};"
        : "+f"(d[0]), "+f"(d[1]), "+f"(d[2]), "+f"(d[3])
        : "r"(a0), "r"(a1), "r"(a2), "r"(a3), "r"(b0), "r"(b1));
}

// pair-interleave within each 8-block: k -> (k<4 ? 2k : 2(k-4)+1)
__device__ __forceinline__ int dperm(int d) {
    const int r = d & 7;
    return (d & ~7) + ((r < 4) ? (2 * r) : (2 * (r - 4) + 1));
}

// ===========================================================================
// Kernel 0: convert x and W to tf32 bit patterns
// ===========================================================================
__global__ void __launch_bounds__(256) tf32_convert_kernel(
    const float* __restrict__ x, const float* __restrict__ w)
{
    const int nx4 = XN / 4;
    const int nw4 = WN / 4;
    const int stride = gridDim.x * blockDim.x;
    for (int i = blockIdx.x * blockDim.x + threadIdx.x; i < nx4 + nw4; i += stride) {
        float4 v;
        float4* dst;
        if (i < nx4) { v = ((const float4*)x)[i]; dst = (float4*)g_xt + i; }
        else         { v = ((const float4*)w)[i - nx4]; dst = (float4*)g_wt + (i - nx4); }
        float4 o;
        o.x = __uint_as_float(f32_to_tf32(v.x));
        o.y = __uint_as_float(f32_to_tf32(v.y));
        o.z = __uint_as_float(f32_to_tf32(v.z));
        o.w = __uint_as_float(f32_to_tf32(v.w));
        *dst = o;
    }
}

// ===========================================================================
// Kernel 1: QKV projection (mma.sync tf32), epilogue writes attention layouts
// ===========================================================================
#define TM 128
#define TN 128
#define NSTG 3
#define LDP 36
#define A_STG_FLTS (TM * LDP)
#define B_STG_FLTS (TN * LDP)
#define STG_FLTS   (A_STG_FLTS + B_STG_FLTS)
#define NCHUNK (CDIM / 32)
#define DYN_SMEM (NSTG * STG_FLTS * 4)
#define Q_PRESCALE (0.125f * 1.44269504f)

__global__ void __launch_bounds__(256, 2) qkv_mma_kernel(
    const float* __restrict__ bias)
{
    extern __shared__ float smem[];

    const int tid = threadIdx.x;
    const int wid = tid >> 5;
    const int lid = tid & 31;
    const int g   = lid >> 2;
    const int c   = lid & 3;
    const int warp_m = (wid & 3) * 32;
    const int warp_n = (wid >> 2) * 64;
    const int m0  = blockIdx.y * TM;
    const int n0  = blockIdx.x * TN;

    const uint32_t sbase = smem_u32(smem);

    const char* gptr[8];
    uint32_t    soff[8];
#pragma unroll
    for (int t = 0; t < 8; t++) {
        const int cc = tid + t * 256;
        if (cc < 1024) {
            const int row = cc >> 3, o = cc & 7;
            gptr[t] = (const char*)(g_xt + (size_t)(m0 + row) * CDIM) + o * 16;
            soff[t] = (uint32_t)(row * LDP * 4 + o * 16);
        } else {
            const int cb = cc - 1024;
            const int row = cb >> 3, o = cb & 7;
            gptr[t] = (const char*)(g_wt + (size_t)(n0 + row) * CDIM) + o * 16;
            soff[t] = (uint32_t)(A_STG_FLTS * 4 + row * LDP * 4 + o * 16);
        }
    }

#define LOAD_STAGE(chunk)                                                   \
    do {                                                                    \
        const uint32_t sb_ = sbase + ((chunk) % NSTG) * (STG_FLTS * 4);     \
        const int gof_ = (chunk) * 128;                                     \
        _Pragma("unroll")                                                   \
        for (int t = 0; t < 8; t++)                                         \
            cp_async16(sb_ + soff[t], gptr[t] + gof_);                      \
        cp_async_commit();                                                  \
    } while (0)

    float acc[2][8][4];
#pragma unroll
    for (int mb = 0; mb < 2; mb++)
#pragma unroll
        for (int nb = 0; nb < 8; nb++)
#pragma unroll
            for (int r = 0; r < 4; r++) acc[mb][nb][r] = 0.f;

    LOAD_STAGE(0);
    LOAD_STAGE(1);

    for (int i = 0; i < NCHUNK; i++) {
        cp_async_wait<NSTG - 2>();
        __syncthreads();

        if (i + 2 < NCHUNK) { LOAD_STAGE(i + 2); }
        else                { cp_async_commit(); }

        const uint32_t* As = (const uint32_t*)(smem + (i % NSTG) * STG_FLTS);
        const uint32_t* Bs = As + A_STG_FLTS;

#pragma unroll
        for (int ks = 0; ks < 4; ks++) {
            const int k = ks * 8;
            uint32_t af[2][4];
#pragma unroll
            for (int mb = 0; mb < 2; mb++) {
                const uint32_t* ap = As + (warp_m + mb * 16 + g) * LDP + k + c;
                af[mb][0] = ap[0];
                af[mb][1] = ap[8 * LDP];
                af[mb][2] = ap[4];
                af[mb][3] = ap[8 * LDP + 4];
            }
            uint32_t bf[8][2];
#pragma unroll
            for (int nb = 0; nb < 8; nb++) {
                const uint32_t* bp = Bs + (warp_n + nb * 8 + g) * LDP + k + c;
                bf[nb][0] = bp[0];
                bf[nb][1] = bp[4];
            }
#pragma unroll
            for (int mb = 0; mb < 2; mb++)
#pragma unroll
                for (int nb = 0; nb < 8; nb++)
                    mma_16n8k8_tf32(acc[mb][nb],
                                    af[mb][0], af[mb][1], af[mb][2], af[mb][3],
                                    bf[nb][0], bf[nb][1]);
        }
        __syncthreads();
    }

    // ---- epilogue ----
    const int which = n0 >> 10;           // 0=Q 1=K 2=V

#pragma unroll
    for (int mb = 0; mb < 2; mb++) {
        const int mA = m0 + warp_m + mb * 16 + g;
        const int mB = mA + 8;
        const int bA = mA >> 11, tA = mA & (TLEN - 1);
        const int bB = mB >> 11, tB = mB & (TLEN - 1);
#pragma unroll
        for (int nb = 0; nb < 8; nb++) {
            const int n = n0 + warp_n + nb * 8 + 2 * c;
            const int h = (n >> 6) & (NHEAD - 1);
            const int d = n & 63;
            const float bx = __ldg(bias + n);
            const float by = __ldg(bias + n + 1);

            if (which == 2) {
                // V: transposed [bh, d, t], tf32-rounded
                float* base = g_v + ((size_t)(bA * NHEAD + h) * HD) * TLEN;
                float* baseB = g_v + ((size_t)(bB * NHEAD + h) * HD) * TLEN;
                base [(size_t)d * TLEN + tA]       = __uint_as_float(f32_to_tf32(acc[mb][nb][0] + bx));
                base [(size_t)(d + 1) * TLEN + tA] = __uint_as_float(f32_to_tf32(acc[mb][nb][1] + by));
                baseB[(size_t)d * TLEN + tB]       = __uint_as_float(f32_to_tf32(acc[mb][nb][2] + bx));
                baseB[(size_t)(d + 1) * TLEN + tB] = __uint_as_float(f32_to_tf32(acc[mb][nb][3] + by));
            } else {
                float* dst = (which == 0) ? g_q : g_k;
                const float sc = (which == 0) ? Q_PRESCALE : 1.0f;
                const int pd0 = dperm(d);
                const int pd1 = dperm(d + 1);
                float* pA = dst + (((size_t)(bA * NHEAD + h) * TLEN) + tA) * HD;
                float* pB = dst + (((size_t)(bB * NHEAD + h) * TLEN) + tB) * HD;
                pA[pd0] = __uint_as_float(f32_to_tf32((acc[mb][nb][0] + bx) * sc));
                pA[pd1] = __uint_as_float(f32_to_tf32((acc[mb][nb][1] + by) * sc));
                pB[pd0] = __uint_as_float(f32_to_tf32((acc[mb][nb][2] + bx) * sc));
                pB[pd1] = __uint_as_float(f32_to_tf32((acc[mb][nb][3] + by) * sc));
            }
        }
    }
}

// ===========================================================================
// Kernel 2: TC causal flash attention — vectorized fragments, 2 CTAs/SM.
//   smem: Q tile [128 x 72] + double-buffered K [64 x 72] and V^T [64 x 72].
//   Stride 72 (== 8 mod 32) -> all LDS.64 fragment patterns conflict-free.
// ===========================================================================
#define ATM 128
#define ATK 64
#define KSTR 72
#define QT_FLTS   (ATM * KSTR)          // 9216
#define KV_T_FLTS (ATK * KSTR)          // 4608
#define ABUF_FLTS (2 * KV_T_FLTS)       // 9216
#define ATTN_SMEM ((QT_FLTS + 2 * ABUF_FLTS) * 4)   // 110592 B

__global__ void __launch_bounds__(256, 2) attn_tc_kernel(float* __restrict__ out)
{
    extern __shared__ float sm[];
    float* SQ = sm;                      // Q tile
    float* SB = sm + QT_FLTS;            // K/V double buffers

    const int tid  = threadIdx.x;
    const int wid  = tid >> 5;
    const int lane = tid & 31;
    const int g    = lane >> 2;
    const int c    = lane & 3;
    const int bh   = blockIdx.y;
    const int b    = bh >> 4;
    const int h    = bh & (NHEAD - 1);
    const int q0   = (gridDim.x - 1 - blockIdx.x) * ATM;
    const int r0l  = wid * 16 + g;        // local q row (0..127)
    const int r0   = q0 + r0l;
    const int r1   = r0 + 8;

    const float* qb  = g_q + (size_t)bh * TLEN * HD;
    const float* kb  = g_k + (size_t)bh * TLEN * HD;
    const float* vtb = g_v + (size_t)bh * HD * TLEN;   // transposed [d][t]

    // ---- load Q tile (one group) ----
    {
        const uint32_t qd = smem_u32(SQ);
#pragma unroll
        for (int i = 0; i < 8; i++) {
            const int id  = tid + i * 256;
            const int row = id >> 4;
            const int o   = id & 15;
            cp_async16(qd + (uint32_t)(row * KSTR + o * 4) * 4,
                       qb + (size_t)(q0 + row) * HD + o * 4);
        }
        cp_async_commit();
    }

    float o[8][4];
#pragma unroll
    for (int nb = 0; nb < 8; nb++)
#pragma unroll
        for (int r = 0; r < 4; r++) o[nb][r] = 0.f;
    float mrow0 = -1e30f, mrow1 = -1e30f;
    float lrow0 = 0.f,    lrow1 = 0.f;

    const int nkt = q0 / ATK + 2;

#define ATTN_LOAD(kt)                                                        \
    do {                                                                     \
        const int j0_ = (kt) * ATK;                                          \
        const uint32_t sd_ = smem_u32(SB) + ((kt) & 1) * (ABUF_FLTS * 4);    \
        _Pragma("unroll")                                                    \
        for (int i_ = 0; i_ < 8; i_++) {                                     \
            const int id_ = tid + i_ * 256;                                  \
            const int row_ = (id_ >> 4) & 63;                                \
            const int o_   = id_ & 15;                                       \
            const float* src_;                                               \
            uint32_t dst_;                                                   \
            if (id_ < 1024) {   /* K: [key][d] */                            \
                src_ = kb + (size_t)(j0_ + row_) * HD + o_ * 4;              \
                dst_ = sd_ + (uint32_t)(row_ * KSTR + o_ * 4) * 4;           \
            } else {            /* V^T: [d][key] */                          \
                src_ = vtb + (size_t)row_ * TLEN + j0_ + o_ * 4;             \
                dst_ = sd_ + KV_T_FLTS * 4                                   \
                     + (uint32_t)(row_ * KSTR + o_ * 4) * 4;                 \
            }                                                                \
            cp_async16(dst_, src_);                                          \
        }                                                                    \
        cp_async_commit();                                                   \
    } while (0)

    ATTN_LOAD(0);

    for (int kt = 0; kt < nkt; kt++) {
        if (kt + 1 < nkt) { ATTN_LOAD(kt + 1); cp_async_wait<1>(); }
        else              { cp_async_wait<0>(); }
        __syncthreads();

        const bool active = (kt * ATK) <= (q0 + wid * 16 + 15);
        if (active) {
            const float* SK = SB + (kt & 1) * ABUF_FLTS;
            const float* SV = SK + KV_T_FLTS;

            // ---- S = Q K^T ----
            float s[8][4];
#pragma unroll
            for (int nb = 0; nb < 8; nb++)
#pragma unroll
                for (int r = 0; r < 4; r++) s[nb][r] = 0.f;

#pragma unroll
            for (int ks = 0; ks < 8; ks++) {
                const int kw = ks * 8 + 2 * c;      // paired word offset
                const float2 qA = *(const float2*)(SQ + r0l * KSTR + kw);
                const float2 qB = *(const float2*)(SQ + (r0l + 8) * KSTR + kw);
                const uint32_t a0 = __float_as_uint(qA.x);
                const uint32_t a2 = __float_as_uint(qA.y);
                const uint32_t a1 = __float_as_uint(qB.x);
                const uint32_t a3 = __float_as_uint(qB.y);
#pragma unroll
                for (int nb = 0; nb < 8; nb++) {
                    const float2 kv = *(const float2*)(SK + (nb * 8 + g) * KSTR + kw);
                    mma_16n8k8_tf32(s[nb], a0, a1, a2, a3,
                                    __float_as_uint(kv.x), __float_as_uint(kv.y));
                }
            }

            // ---- causal mask (last two tiles only) ----
            if (kt >= nkt - 2) {
                const int j0 = kt * ATK;
#pragma unroll
                for (int nb = 0; nb < 8; nb++) {
                    const int jA = j0 + nb * 8 + 2 * c;
                    if (jA     > r0) s[nb][0] = -1e30f;
                    if (jA + 1 > r0) s[nb][1] = -1e30f;
                    if (jA     > r1) s[nb][2] = -1e30f;
                    if (jA + 1 > r1) s[nb][3] = -1e30f;
                }
            }

            // ---- online softmax (base 2) ----
            float t0 = -1e30f, t1 = -1e30f;
#pragma unroll
            for (int nb = 0; nb < 8; nb++) {
                t0 = fmaxf(t0, fmaxf(s[nb][0], s[nb][1]));
                t1 = fmaxf(t1, fmaxf(s[nb][2], s[nb][3]));
            }
            t0 = fmaxf(t0, __shfl_xor_sync(0xffffffffu, t0, 1));
            t0 = fmaxf(t0, __shfl_xor_sync(0xffffffffu, t0, 2));
            t1 = fmaxf(t1, __shfl_xor_sync(0xffffffffu, t1, 1));
            t1 = fmaxf(t1, __shfl_xor_sync(0xffffffffu, t1, 2));

            const float mn0 = fmaxf(mrow0, t0);
            const float mn1 = fmaxf(mrow1, t1);
            const float a0s = ex2f(mrow0 - mn0);
            const float a1s = ex2f(mrow1 - mn1);
            mrow0 = mn0; mrow1 = mn1;
            lrow0 *= a0s; lrow1 *= a1s;
#pragma unroll
            for (int nb = 0; nb < 8; nb++) {
                o[nb][0] *= a0s; o[nb][1] *= a0s;
                o[nb][2] *= a1s; o[nb][3] *= a1s;
            }

#pragma unroll
            for (int nb = 0; nb < 8; nb++) {
                const float p0 = ex2f(s[nb][0] - mn0);
                const float p1 = ex2f(s[nb][1] - mn0);
                const float p2 = ex2f(s[nb][2] - mn1);
                const float p3 = ex2f(s[nb][3] - mn1);
                lrow0 += p0 + p1;
                lrow1 += p2 + p3;
                s[nb][0] = __uint_as_float(f32_to_tf32(p0));
                s[nb][1] = __uint_as_float(f32_to_tf32(p1));
                s[nb][2] = __uint_as_float(f32_to_tf32(p2));
                s[nb][3] = __uint_as_float(f32_to_tf32(p3));
            }

            // ---- O += P V (V^T rows = d; keys 2c,2c+1 adjacent -> LDS.64) ----
#pragma unroll
            for (int kbk = 0; kbk < 8; kbk++) {
                const uint32_t pa0 = __float_as_uint(s[kbk][0]);
                const uint32_t pa1 = __float_as_uint(s[kbk][2]);
                const uint32_t pa2 = __float_as_uint(s[kbk][1]);
                const uint32_t pa3 = __float_as_uint(s[kbk][3]);
                const int kw = kbk * 8 + 2 * c;
#pragma unroll
                for (int nb = 0; nb < 8; nb++) {
                    const float2 vv = *(const float2*)(SV + (nb * 8 + g) * KSTR + kw);
                    mma_16n8k8_tf32(o[nb], pa0, pa1, pa2, pa3,
                                    __float_as_uint(vv.x), __float_as_uint(vv.y));
                }
            }
        }
        __syncthreads();
    }

    // ---- finalize ----
    lrow0 += __shfl_xor_sync(0xffffffffu, lrow0, 1);
    lrow0 += __shfl_xor_sync(0xffffffffu, lrow0, 2);
    lrow1 += __shfl_xor_sync(0xffffffffu, lrow1, 1);
    lrow1 += __shfl_xor_sync(0xffffffffu, lrow1, 2);
    const float inv0 = 1.f / lrow0;
    const float inv1 = 1.f / lrow1;

    float* orow0 = out + ((size_t)b * TLEN + r0) * CDIM + h * HD;
    float* orow1 = out + ((size_t)b * TLEN + r1) * CDIM + h * HD;
#pragma unroll
    for (int nb = 0; nb < 8; nb++) {
        const int d = nb * 8 + 2 * c;
        *(float2*)(orow0 + d) = make_float2(o[nb][0] * inv0, o[nb][1] * inv0);
        *(float2*)(orow1 + d) = make_float2(o[nb][2] * inv1, o[nb][3] * inv1);
    }
}

// ---------------------------------------------------------------------------
extern "C" void kernel_launch(void* const* d_in, const int* in_sizes, int n_in,
                              void* d_out, int out_size)
{
    const float* x    = (const float*)d_in[0];
    const float* w    = (const float*)d_in[1];
    const float* bias = (const float*)d_in[2];
    float* out        = (float*)d_out;

    (void)in_sizes; (void)n_in; (void)out_size;

    cudaFuncSetAttribute(qkv_mma_kernel,
                         cudaFuncAttributeMaxDynamicSharedMemorySize, DYN_SMEM);
    cudaFuncSetAttribute(attn_tc_kernel,
                         cudaFuncAttributeMaxDynamicSharedMemorySize, ATTN_SMEM);

    tf32_convert_kernel<<<1184, 256>>>(x, w);

    dim3 ggrid(3 * CDIM / TN, (BSZ * TLEN) / TM);   // (24, 64)
    qkv_mma_kernel<<<ggrid, 256, DYN_SMEM>>>(bias);

    dim3 agrid(TLEN / ATM, BSZ * NHEAD);            // (16, 64)
    attn_tc_kernel<<<agrid, 256, ATTN_SMEM>>>(out);
}

// round 9
// speedup vs baseline: 8.1596x; 1.6966x over previous
#include <cuda_runtime.h>
#include <cuda_fp16.h>
#include <math.h>
#include <stdint.h>

#define BSZ   4
#define TLEN  2048
#define CDIM  1024
#define NHEAD 16
#define HD    64

#define SCRATCH_ELEMS (BSZ * NHEAD * TLEN * HD)   // 8,388,608
#define XN (BSZ * TLEN * CDIM)
#define WN (3 * CDIM * CDIM)

// g_q, g_k: fp16 [bh][t][d'] with d' quad-interleaved within 16-blocks
//           ({2c,2c+1,2c+8,2c+9} -> {4c..4c+3}); Q pre-scaled by 0.125*log2e.
// g_v:      fp16 TRANSPOSED [bh][d][t'] with t' quad-interleaved likewise.
// g_xt/g_wt: x / W as fp16 with k-dim quad-interleaved.
__device__ __half g_q[SCRATCH_ELEMS];
__device__ __half g_k[SCRATCH_ELEMS];
__device__ __half g_v[SCRATCH_ELEMS];
__device__ __half g_xt[XN];
__device__ __half g_wt[WN];

// ===========================================================================
// Helpers
// ===========================================================================
__device__ __forceinline__ uint32_t smem_u32(const void* p) {
    uint32_t a;
    asm("{ .reg .u64 t; cvta.to.shared.u64 t, %1; cvt.u32.u64 %0, t; }"
        : "=r"(a) : "l"(p));
    return a;
}

__device__ __forceinline__ void cp_async16(uint32_t saddr, const void* gaddr) {
    asm volatile("cp.async.cg.shared.global [%0], [%1], 16;"
                 :: "r"(saddr), "l"(gaddr) : "memory");
}
__device__ __forceinline__ void cp_async_commit() {
    asm volatile("cp.async.commit_group;" ::: "memory");
}
template <int N>
__device__ __forceinline__ void cp_async_wait() {
    asm volatile("cp.async.wait_group %0;" :: "n"(N) : "memory");
}

__device__ __forceinline__ float ex2f(float x) {
    float y;
    asm("ex2.approx.ftz.f32 %0, %1;" : "=f"(y) : "f"(x));
    return y;
}

// D(16x8) += A(16x16 row) * B(16x8 col), fp16 in, fp32 accumulate
__device__ __forceinline__ void mma_16816_f16(
    float* d, uint32_t a0, uint32_t a1, uint32_t a2, uint32_t a3,
    uint32_t b0, uint32_t b1)
{
    asm volatile(
        "mma.sync.aligned.m16n8k16.row.col.f32.f16.f16.f32 "
        "{%0,%1,%2,%3}, {%4,%5,%6,%7}, {%8,%9}, {%0,%1,%2,%3};"
        : "+f"(d[0]), "+f"(d[1]), "+f"(d[2]), "+f"(d[3])
        : "r"(a0), "r"(a1), "r"(a2), "r"(a3), "r"(b0), "r"(b1));
}

// quad-interleave within 16-block: k -> 4*((k&7)>>1) + 2*((k>>3)&1) + (k&1)
__device__ __forceinline__ int qperm(int k) {
    return (k & ~15) + 4 * ((k & 7) >> 1) + 2 * ((k >> 3) & 1) + (k & 1);
}

__device__ __forceinline__ uint32_t h2u(half2 h) {
    return *(uint32_t*)&h;
}

// ===========================================================================
// Kernel 0: convert x and W to fp16 with k-quad-interleave
// ===========================================================================
__global__ void __launch_bounds__(256) cvt_kernel(
    const float* __restrict__ x, const float* __restrict__ w)
{
    const int nx4 = XN / 4;
    const int nw4 = WN / 4;
    const int stride = gridDim.x * blockDim.x;
    for (int i = blockIdx.x * blockDim.x + threadIdx.x; i < nx4 + nw4; i += stride) {
        float4 v;
        __half* dst;
        int base;
        if (i < nx4) { v = ((const float4*)x)[i]; dst = g_xt; base = i * 4; }
        else         { v = ((const float4*)w)[i - nx4]; dst = g_wt; base = (i - nx4) * 4; }
        const int b16 = base & ~15;
        const int o   = base & 15;          // 0,4,8,12
        const float vv[4] = {v.x, v.y, v.z, v.w};
#pragma unroll
        for (int p = 0; p < 2; p++) {
            const int k = o + 2 * p;
            const int d = b16 + 4 * ((k & 7) >> 1) + 2 * ((k >> 3) & 1);
            *(half2*)(dst + d) = __floats2half2_rn(vv[2 * p], vv[2 * p + 1]);
        }
    }
}

// ===========================================================================
// Kernel 1: QKV projection, fp16 m16n8k16. CTA 128x128, warp 32x64, TK=32.
// ===========================================================================
#define TM 128
#define TN 128
#define NSTG 3
#define LDH 48                                // halves per row (only 32 used)
#define A_STG_H (TM * LDH)                    // 6144 halves
#define STG_H   (2 * A_STG_H)                 // A + B
#define NCHUNK (CDIM / 32)                    // 32
#define DYN_SMEM (NSTG * STG_H * 2)           // 73728 B
#define Q_PRESCALE (0.125f * 1.44269504f)

__global__ void __launch_bounds__(256, 2) qkv_mma_kernel(
    const float* __restrict__ bias)
{
    extern __shared__ __half smh[];

    const int tid = threadIdx.x;
    const int wid = tid >> 5;
    const int lid = tid & 31;
    const int g   = lid >> 2;
    const int c   = lid & 3;
    const int warp_m = (wid & 3) * 32;
    const int warp_n = (wid >> 2) * 64;
    const int m0  = blockIdx.y * TM;
    const int n0  = blockIdx.x * TN;

    const uint32_t sbase = smem_u32(smh);

    // cp.async mapping: 1024 x 16B chunks per stage, 4 per thread
    const char* gptr[4];
    uint32_t    soff[4];
#pragma unroll
    for (int t = 0; t < 4; t++) {
        const int cc = tid + t * 256;
        if (cc < 512) {
            const int row = cc >> 2, o = cc & 3;
            gptr[t] = (const char*)(g_xt + (size_t)(m0 + row) * CDIM) + o * 16;
            soff[t] = (uint32_t)(row * LDH * 2 + o * 16);
        } else {
            const int cb = cc - 512;
            const int row = cb >> 2, o = cb & 3;
            gptr[t] = (const char*)(g_wt + (size_t)(n0 + row) * CDIM) + o * 16;
            soff[t] = (uint32_t)(A_STG_H * 2 + row * LDH * 2 + o * 16);
        }
    }

#define LOAD_STAGE(chunk)                                                   \
    do {                                                                    \
        const uint32_t sb_ = sbase + ((chunk) % NSTG) * (STG_H * 2);        \
        const int gof_ = (chunk) * 64;   /* 32 halves */                    \
        _Pragma("unroll")                                                   \
        for (int t = 0; t < 4; t++)                                         \
            cp_async16(sb_ + soff[t], gptr[t] + gof_);                      \
        cp_async_commit();                                                  \
    } while (0)

    float acc[2][8][4];
#pragma unroll
    for (int mb = 0; mb < 2; mb++)
#pragma unroll
        for (int nb = 0; nb < 8; nb++)
#pragma unroll
            for (int r = 0; r < 4; r++) acc[mb][nb][r] = 0.f;

    LOAD_STAGE(0);
    LOAD_STAGE(1);

    for (int i = 0; i < NCHUNK; i++) {
        cp_async_wait<NSTG - 2>();
        __syncthreads();

        if (i + 2 < NCHUNK) { LOAD_STAGE(i + 2); }
        else                { cp_async_commit(); }

        const __half* As = smh + (i % NSTG) * STG_H;
        const __half* Bs = As + A_STG_H;

#pragma unroll
        for (int ks = 0; ks < 2; ks++) {        // two k16 steps per 32-chunk
            const int ho = ks * 16 + 4 * c;     // interleaved quad offset
            uint32_t afl[2][2], afh[2][2];
#pragma unroll
            for (int mb = 0; mb < 2; mb++) {
                const uint2 lo = *(const uint2*)(As + (warp_m + mb * 16 + g) * LDH + ho);
                const uint2 hi = *(const uint2*)(As + (warp_m + mb * 16 + g + 8) * LDH + ho);
                afl[mb][0] = lo.x; afl[mb][1] = lo.y;   // a0, a2
                afh[mb][0] = hi.x; afh[mb][1] = hi.y;   // a1, a3
            }
            uint32_t bf[8][2];
#pragma unroll
            for (int nb = 0; nb < 8; nb++) {
                const uint2 bb = *(const uint2*)(Bs + (warp_n + nb * 8 + g) * LDH + ho);
                bf[nb][0] = bb.x; bf[nb][1] = bb.y;
            }
#pragma unroll
            for (int mb = 0; mb < 2; mb++)
#pragma unroll
                for (int nb = 0; nb < 8; nb++)
                    mma_16816_f16(acc[mb][nb],
                                  afl[mb][0], afh[mb][0], afl[mb][1], afh[mb][1],
                                  bf[nb][0], bf[nb][1]);
        }
        __syncthreads();
    }

    // ---- epilogue ----
    const int which = n0 >> 10;                 // 0=Q 1=K 2=V

#pragma unroll
    for (int mb = 0; mb < 2; mb++) {
        const int mA = m0 + warp_m + mb * 16 + g;
        const int mB = mA + 8;
        const int bA = mA >> 11, tA = mA & (TLEN - 1);
        const int bB = mB >> 11, tB = mB & (TLEN - 1);
#pragma unroll
        for (int nb = 0; nb < 8; nb++) {
            const int n = n0 + warp_n + nb * 8 + 2 * c;
            const int h = (n >> 6) & (NHEAD - 1);
            const int d = n & 63;
            const float bx = __ldg(bias + n);
            const float by = __ldg(bias + n + 1);

            if (which == 2) {
                // V^T: [bh][d][t'], t' quad-interleaved
                const int ptA = qperm(tA);
                const int ptB = qperm(tB);
                __half* baseA = g_v + ((size_t)(bA * NHEAD + h) * HD) * TLEN;
                __half* baseB = g_v + ((size_t)(bB * NHEAD + h) * HD) * TLEN;
                baseA[(size_t)d * TLEN + ptA]       = __float2half_rn(acc[mb][nb][0] + bx);
                baseA[(size_t)(d + 1) * TLEN + ptA] = __float2half_rn(acc[mb][nb][1] + by);
                baseB[(size_t)d * TLEN + ptB]       = __float2half_rn(acc[mb][nb][2] + bx);
                baseB[(size_t)(d + 1) * TLEN + ptB] = __float2half_rn(acc[mb][nb][3] + by);
            } else {
                __half* dst = (which == 0) ? g_q : g_k;
                const float sc = (which == 0) ? Q_PRESCALE : 1.0f;
                const int pd = qperm(d);        // d even -> pd, pd+1 adjacent
                __half* pA = dst + (((size_t)(bA * NHEAD + h) * TLEN) + tA) * HD + pd;
                __half* pB = dst + (((size_t)(bB * NHEAD + h) * TLEN) + tB) * HD + pd;
                *(half2*)pA = __floats2half2_rn((acc[mb][nb][0] + bx) * sc,
                                                (acc[mb][nb][1] + by) * sc);
                *(half2*)pB = __floats2half2_rn((acc[mb][nb][2] + bx) * sc,
                                                (acc[mb][nb][3] + by) * sc);
            }
        }
    }
}

// ===========================================================================
// Kernel 2: fp16 TC causal flash attention.
//   CTA = 8 warps = 128 q rows; K/V tiles of 128 keys (two 64-key halves),
//   double-buffered cp.async; Q tile resident in smem. 2 CTAs/SM.
//   Row strides: Q/K 80 halves (>= 64-half row, 40 words == 8 mod 32),
//                V^T 144 halves (>= 128-key row, 72 words == 8 mod 32).
// ===========================================================================
#define ATM 128
#define ATK 128
#define QSTR 80                        // halves per Q/K row (160 B)
#define KSTR 80
#define VSTR 144                       // halves per V^T row (288 B)
#define QT_H (ATM * QSTR)              // 10240
#define KT_H (ATK * KSTR)              // 10240
#define VT_H (HD * VSTR)               // 9216
#define BUF_H (KT_H + VT_H)            // 19456
#define ATTN_SMEM ((QT_H + 2 * BUF_H) * 2)   // 98304 B

__global__ void __launch_bounds__(256, 2) attn_tc_kernel(float* __restrict__ out)
{
    extern __shared__ __half smh[];
    __half* SQ = smh;
    __half* SB = smh + QT_H;

    const int tid  = threadIdx.x;
    const int wid  = tid >> 5;
    const int lane = tid & 31;
    const int g    = lane >> 2;
    const int c    = lane & 3;
    const int bh   = blockIdx.y;
    const int b    = bh >> 4;
    const int h    = bh & (NHEAD - 1);
    const int q0   = (gridDim.x - 1 - blockIdx.x) * ATM;   // heavy first
    const int r0l  = wid * 16 + g;
    const int r0   = q0 + r0l;
    const int r1   = r0 + 8;

    const __half* qb  = g_q + (size_t)bh * TLEN * HD;
    const __half* kb  = g_k + (size_t)bh * TLEN * HD;
    const __half* vtb = g_v + (size_t)bh * HD * TLEN;

    // ---- Q tile: 128 rows x 128 B (8 chunks/row), 4 chunks/thread ----
    {
        const uint32_t qd = smem_u32(SQ);
#pragma unroll
        for (int i = 0; i < 4; i++) {
            const int id  = tid + i * 256;
            const int row = id >> 3;
            const int o   = id & 7;
            cp_async16(qd + (uint32_t)(row * QSTR * 2 + o * 16),
                       qb + (size_t)(q0 + row) * HD + o * 8);
        }
        cp_async_commit();
    }

    float o[8][4];
#pragma unroll
    for (int nb = 0; nb < 8; nb++)
#pragma unroll
        for (int r = 0; r < 4; r++) o[nb][r] = 0.f;
    float mrow0 = -1e30f, mrow1 = -1e30f;
    float lrow0 = 0.f,    lrow1 = 0.f;

    const int nkt = q0 / ATK + 1;

    // K: 128 keys x 128 B (8 chunks/row); V^T: 64 d x 256 B (16 chunks/row)
#define ATTN_LOAD(kt)                                                        \
    do {                                                                     \
        const int j0_ = (kt) * ATK;                                          \
        const uint32_t sd_ = smem_u32(SB) + ((kt) & 1) * (BUF_H * 2);        \
        _Pragma("unroll")                                                    \
        for (int i_ = 0; i_ < 8; i_++) {                                     \
            const int id_ = tid + i_ * 256;                                  \
            const __half* src_;                                              \
            uint32_t dst_;                                                   \
            if (id_ < 1024) {                                                \
                const int row_ = id_ >> 3, o_ = id_ & 7;                     \
                src_ = kb + (size_t)(j0_ + row_) * HD + o_ * 8;              \
                dst_ = sd_ + (uint32_t)(row_ * KSTR * 2 + o_ * 16);          \
            } else {                                                         \
                const int id2_ = id_ - 1024;                                 \
                const int row_ = id2_ >> 4, o_ = id2_ & 15;                  \
                src_ = vtb + (size_t)row_ * TLEN + j0_ + o_ * 8;             \
                dst_ = sd_ + KT_H * 2                                        \
                     + (uint32_t)(row_ * VSTR * 2 + o_ * 16);                \
            }                                                                \
            cp_async16(dst_, src_);                                          \
        }                                                                    \
        cp_async_commit();                                                   \
    } while (0)

    ATTN_LOAD(0);

    for (int kt = 0; kt < nkt; kt++) {
        if (kt + 1 < nkt) { ATTN_LOAD(kt + 1); cp_async_wait<1>(); }
        else              { cp_async_wait<0>(); }
        __syncthreads();

        const __half* SK = SB + (kt & 1) * BUF_H;
        const __half* SV = SK + KT_H;
        const bool last = (kt == nkt - 1);

#pragma unroll
        for (int hf = 0; hf < 2; hf++) {
            const int j0h = kt * ATK + hf * 64;
            if (j0h > q0 + wid * 16 + 15) break;   // warp fully masked

            // ---- S = Q K^T (16 x 64) ----
            float s[8][4];
#pragma unroll
            for (int nb = 0; nb < 8; nb++)
#pragma unroll
                for (int r = 0; r < 4; r++) s[nb][r] = 0.f;

#pragma unroll
            for (int ks = 0; ks < 4; ks++) {
                const int ho = ks * 16 + 4 * c;
                const uint2 qA = *(const uint2*)(SQ + r0l * QSTR + ho);
                const uint2 qB = *(const uint2*)(SQ + (r0l + 8) * QSTR + ho);
#pragma unroll
                for (int nb = 0; nb < 8; nb++) {
                    const uint2 kk = *(const uint2*)(SK + (hf * 64 + nb * 8 + g) * KSTR + ho);
                    mma_16816_f16(s[nb], qA.x, qB.x, qA.y, qB.y, kk.x, kk.y);
                }
            }

            // ---- causal mask (last tile only) ----
            if (last) {
#pragma unroll
                for (int nb = 0; nb < 8; nb++) {
                    const int jA = j0h + nb * 8 + 2 * c;
                    if (jA     > r0) s[nb][0] = -1e30f;
                    if (jA + 1 > r0) s[nb][1] = -1e30f;
                    if (jA     > r1) s[nb][2] = -1e30f;
                    if (jA + 1 > r1) s[nb][3] = -1e30f;
                }
            }

            // ---- online softmax (base 2) ----
            float t0 = -1e30f, t1 = -1e30f;
#pragma unroll
            for (int nb = 0; nb < 8; nb++) {
                t0 = fmaxf(t0, fmaxf(s[nb][0], s[nb][1]));
                t1 = fmaxf(t1, fmaxf(s[nb][2], s[nb][3]));
            }
            t0 = fmaxf(t0, __shfl_xor_sync(0xffffffffu, t0, 1));
            t0 = fmaxf(t0, __shfl_xor_sync(0xffffffffu, t0, 2));
            t1 = fmaxf(t1, __shfl_xor_sync(0xffffffffu, t1, 1));
            t1 = fmaxf(t1, __shfl_xor_sync(0xffffffffu, t1, 2));

            const float mn0 = fmaxf(mrow0, t0);
            const float mn1 = fmaxf(mrow1, t1);
            const float a0s = ex2f(mrow0 - mn0);
            const float a1s = ex2f(mrow1 - mn1);
            mrow0 = mn0; mrow1 = mn1;
            lrow0 *= a0s; lrow1 *= a1s;
#pragma unroll
            for (int nb = 0; nb < 8; nb++) {
                o[nb][0] *= a0s; o[nb][1] *= a0s;
                o[nb][2] *= a1s; o[nb][3] *= a1s;
            }

#pragma unroll
            for (int nb = 0; nb < 8; nb++) {
                s[nb][0] = ex2f(s[nb][0] - mn0);
                s[nb][1] = ex2f(s[nb][1] - mn0);
                s[nb][2] = ex2f(s[nb][2] - mn1);
                s[nb][3] = ex2f(s[nb][3] - mn1);
                lrow0 += s[nb][0] + s[nb][1];
                lrow1 += s[nb][2] + s[nb][3];
            }

            // ---- O += P V:  P(16x64) packed from S, V^T key-interleaved ----
#pragma unroll
            for (int kbk = 0; kbk < 4; kbk++) {     // 4 k16 blocks of keys
                const uint32_t pa0 = h2u(__floats2half2_rn(s[2*kbk][0],   s[2*kbk][1]));
                const uint32_t pa1 = h2u(__floats2half2_rn(s[2*kbk][2],   s[2*kbk][3]));
                const uint32_t pa2 = h2u(__floats2half2_rn(s[2*kbk+1][0], s[2*kbk+1][1]));
                const uint32_t pa3 = h2u(__floats2half2_rn(s[2*kbk+1][2], s[2*kbk+1][3]));
                const int vo = hf * 64 + kbk * 16 + 4 * c;
#pragma unroll
                for (int nb = 0; nb < 8; nb++) {
                    const uint2 vv = *(const uint2*)(SV + (nb * 8 + g) * VSTR + vo);
                    mma_16816_f16(o[nb], pa0, pa1, pa2, pa3, vv.x, vv.y);
                }
            }
        }
        __syncthreads();
    }

    // ---- finalize ----
    lrow0 += __shfl_xor_sync(0xffffffffu, lrow0, 1);
    lrow0 += __shfl_xor_sync(0xffffffffu, lrow0, 2);
    lrow1 += __shfl_xor_sync(0xffffffffu, lrow1, 1);
    lrow1 += __shfl_xor_sync(0xffffffffu, lrow1, 2);
    const float inv0 = 1.f / lrow0;
    const float inv1 = 1.f / lrow1;

    float* orow0 = out + ((size_t)b * TLEN + r0) * CDIM + h * HD;
    float* orow1 = out + ((size_t)b * TLEN + r1) * CDIM + h * HD;
#pragma unroll
    for (int nb = 0; nb < 8; nb++) {
        const int d = nb * 8 + 2 * c;
        *(float2*)(orow0 + d) = make_float2(o[nb][0] * inv0, o[nb][1] * inv0);
        *(float2*)(orow1 + d) = make_float2(o[nb][2] * inv1, o[nb][3] * inv1);
    }
}

// ---------------------------------------------------------------------------
extern "C" void kernel_launch(void* const* d_in, const int* in_sizes, int n_in,
                              void* d_out, int out_size)
{
    const float* x    = (const float*)d_in[0];
    const float* w    = (const float*)d_in[1];
    const float* bias = (const float*)d_in[2];
    float* out        = (float*)d_out;

    (void)in_sizes; (void)n_in; (void)out_size;

    cudaFuncSetAttribute(qkv_mma_kernel,
                         cudaFuncAttributeMaxDynamicSharedMemorySize, DYN_SMEM);
    cudaFuncSetAttribute(attn_tc_kernel,
                         cudaFuncAttributeMaxDynamicSharedMemorySize, ATTN_SMEM);

    cvt_kernel<<<1184, 256>>>(x, w);

    dim3 ggrid(3 * CDIM / TN, (BSZ * TLEN) / TM);   // (24, 64)
    qkv_mma_kernel<<<ggrid, 256, DYN_SMEM>>>(bias);

    dim3 agrid(TLEN / ATM, BSZ * NHEAD);            // (16, 64)
    attn_tc_kernel<<<agrid, 256, ATTN_SMEM>>>(out);
}